// round 6
// baseline (speedup 1.0000x reference)
#include <cuda_runtime.h>
#include <cuda_bf16.h>
#include <math.h>
#include <stdint.h>

// ---------------------------------------------------------------------------
// Problem constants
// ---------------------------------------------------------------------------
#define TOK   50176      // 2*8*56*56
#define CDIM  128
#define CH    512
#define NWIN  512        // 2 * 4*8*8
#define NTOK  98         // 2*7*7
#define NH    4
#define HD    32
#define QKVN  384

typedef __nv_bfloat16  bf16;
typedef __nv_bfloat162 bf162;

// ---------------------------------------------------------------------------
// Scratch (device globals: allocation-free, graph-capture safe)
// ---------------------------------------------------------------------------
__device__ bf16  g_xw  [(size_t)TOK * CDIM];   // LN1 out (window order) / LN2 out (spatial)
__device__ bf16  g_qkv [(size_t)TOK * QKVN];   // qkv, window order
__device__ bf16  g_attn[(size_t)TOK * CDIM];   // attention out, window order
__device__ float g_x2  [(size_t)TOK * CDIM];   // x + proj (spatial, fp32)
__device__ bf16  g_h   [(size_t)TOK * CH];     // fc1 output
__device__ float g_bias[NH * NTOK * NTOK];     // gathered attention bias (fp32)
// bf16 weights
__device__ bf16  g_wq[QKVN * CDIM];
__device__ bf16  g_wp[CDIM * CDIM];
__device__ bf16  g_w1[CH * CDIM];
__device__ bf16  g_w2[CDIM * CH];

// ---------------------------------------------------------------------------
// index helpers
// ---------------------------------------------------------------------------
__device__ __forceinline__ long win_to_spatial(long row) {
    int w = (int)(row / NTOK);
    int n = (int)(row % NTOK);
    int b   = w >> 8;
    int rem = w & 255;
    int wdi = rem >> 6, whi = (rem >> 3) & 7, wwi = rem & 7;
    int zd = n / 49; int r2 = n % 49; int zh = r2 / 7, zw = r2 % 7;
    int d  = wdi * 2 + zd;
    int hh = whi * 7 + zh;
    int xx = wwi * 7 + zw;
    return (((long)(b * 8 + d) * 56) + hh) * 56 + xx;
}

__device__ __forceinline__ long spatial_to_win(long t) {
    int b  = (int)(t / 25088);
    int r  = (int)(t % 25088);
    int d  = r / 3136; r %= 3136;
    int hh = r / 56;
    int xx = r % 56;
    int widx = ((b * 4 + (d >> 1)) * 8 + hh / 7) * 8 + xx / 7;
    int n    = ((d & 1) * 7 + hh % 7) * 7 + xx % 7;
    return (long)widx * NTOK + n;
}

// ---------------------------------------------------------------------------
// async copy + ldmatrix + mma helpers
// ---------------------------------------------------------------------------
__device__ __forceinline__ void cp_async16(bf16* smem_dst, const bf16* gmem_src) {
    uint32_t s = (uint32_t)__cvta_generic_to_shared(smem_dst);
    asm volatile("cp.async.cg.shared.global [%0], [%1], 16;\n" :: "r"(s), "l"(gmem_src));
}
__device__ __forceinline__ void cp_commit() { asm volatile("cp.async.commit_group;\n"); }
template<int N>
__device__ __forceinline__ void cp_wait() { asm volatile("cp.async.wait_group %0;\n" :: "n"(N)); }

__device__ __forceinline__ void ldsm_x4(uint32_t r[4], const bf16* p) {
    uint32_t a = (uint32_t)__cvta_generic_to_shared(p);
    asm volatile("ldmatrix.sync.aligned.m8n8.x4.shared.b16 {%0,%1,%2,%3}, [%4];\n"
                 : "=r"(r[0]), "=r"(r[1]), "=r"(r[2]), "=r"(r[3]) : "r"(a));
}
__device__ __forceinline__ void ldsm_x4_t(uint32_t r[4], const bf16* p) {
    uint32_t a = (uint32_t)__cvta_generic_to_shared(p);
    asm volatile("ldmatrix.sync.aligned.m8n8.x4.trans.shared.b16 {%0,%1,%2,%3}, [%4];\n"
                 : "=r"(r[0]), "=r"(r[1]), "=r"(r[2]), "=r"(r[3]) : "r"(a));
}
__device__ __forceinline__ void mma_bf16(float c[4], const uint32_t a[4], const uint32_t b[2]) {
    asm volatile(
        "mma.sync.aligned.m16n8k16.row.col.f32.bf16.bf16.f32 "
        "{%0,%1,%2,%3}, {%4,%5,%6,%7}, {%8,%9}, {%0,%1,%2,%3};\n"
        : "+f"(c[0]), "+f"(c[1]), "+f"(c[2]), "+f"(c[3])
        : "r"(a[0]), "r"(a[1]), "r"(a[2]), "r"(a[3]), "r"(b[0]), "r"(b[1]));
}

// ---------------------------------------------------------------------------
// fused weight conversion fp32 -> bf16 (float4 granularity)
// ---------------------------------------------------------------------------
__global__ void cvt_weights_kernel(const float* __restrict__ wq,
                                   const float* __restrict__ wp,
                                   const float* __restrict__ w1,
                                   const float* __restrict__ w2) {
    int i = blockIdx.x * blockDim.x + threadIdx.x;   // float4 index, total 49152
    const float* src; bf16* dst; int off;
    if (i < 12288)      { src = wq; dst = g_wq; off = i; }
    else if (i < 16384) { src = wp; dst = g_wp; off = i - 12288; }
    else if (i < 32768) { src = w1; dst = g_w1; off = i - 16384; }
    else                { src = w2; dst = g_w2; off = i - 32768; }
    float4 v = *(const float4*)(src + off * 4);
    bf162 p0 = __float22bfloat162_rn(make_float2(v.x, v.y));
    bf162 p1 = __float22bfloat162_rn(make_float2(v.z, v.w));
    uint2 u = make_uint2(*(uint32_t*)&p0, *(uint32_t*)&p1);
    *(uint2*)(dst + off * 4) = u;
}

// ---------------------------------------------------------------------------
// bias gather: g_bias[h][n][m] = bias_table[rel_index[n][m]][h]
// ---------------------------------------------------------------------------
__global__ void bias_gather_kernel(const float* __restrict__ bias_table,
                                   const int* __restrict__ rel_index) {
    int m = threadIdx.x;
    int n = blockIdx.x;
    int h = blockIdx.y;
    int idx = rel_index[n * NTOK + m];
    g_bias[(h * NTOK + n) * NTOK + m] = bias_table[idx * NH + h];
}

// ---------------------------------------------------------------------------
// LayerNorm over C=128 (fp32 in, bf16 out): one warp per token.
// ---------------------------------------------------------------------------
template<bool PERMUTE>
__global__ __launch_bounds__(256)
void ln_kernel(const float* __restrict__ in,
               const float* __restrict__ gam,
               const float* __restrict__ bet,
               bf16* __restrict__ out) {
    int warp = threadIdx.x >> 5;
    int lane = threadIdx.x & 31;
    long t = (long)blockIdx.x * 8 + warp;
    const float4 v = *(const float4*)(in + t * CDIM + lane * 4);
    float s  = v.x + v.y + v.z + v.w;
    float sq = v.x * v.x + v.y * v.y + v.z * v.z + v.w * v.w;
    #pragma unroll
    for (int o = 16; o; o >>= 1) {
        s  += __shfl_xor_sync(0xffffffffu, s,  o);
        sq += __shfl_xor_sync(0xffffffffu, sq, o);
    }
    float mean = s * (1.0f / CDIM);
    float var  = sq * (1.0f / CDIM) - mean * mean;
    float rstd = rsqrtf(var + 1e-5f);
    const float4 g = *(const float4*)(gam + lane * 4);
    const float4 b = *(const float4*)(bet + lane * 4);
    bf162 p0 = __float22bfloat162_rn(make_float2((v.x - mean) * rstd * g.x + b.x,
                                                 (v.y - mean) * rstd * g.y + b.y));
    bf162 p1 = __float22bfloat162_rn(make_float2((v.z - mean) * rstd * g.z + b.z,
                                                 (v.w - mean) * rstd * g.w + b.w));
    long orow = PERMUTE ? spatial_to_win(t) : t;
    uint2 u = make_uint2(*(uint32_t*)&p0, *(uint32_t*)&p1);
    *(uint2*)(out + orow * CDIM + lane * 4) = u;
}

// ---------------------------------------------------------------------------
// BF16 tensor-core GEMM v4 (single-barrier mainloop):
// C[M,N] = A[M,K] @ W[N,K]^T (+ epilogue). Block 128x128.
// Whole 128-wide K-panel resident in smem: load all -> wait -> ONE sync ->
// 8 barrier-free k16 steps. K>128 handled as outer chunks of 128.
// 256 threads (8 warps: 2x4), warp tile 64x32, m16n8k16 + ldmatrix.x4.
// MODE 0: qkv  -> +bias; scale q-part; bf16 out [M,384]
// MODE 1: proj -> +bias; permute; += resid(x); fp32 g_x2  AND fused LN2 -> bf16 g_xw
// MODE 2: fc1  -> +bias; exact GELU; bf16 out [M,512]
// MODE 3: fc2  -> +bias; += resid(g_x2); fp32 out d_out
// ---------------------------------------------------------------------------
#define GS 136                 // smem row stride in halves: 128 + 8 pad (odd 16B stride)
template<int MODE, int KT>
__global__ __launch_bounds__(256, 2)
void gemm_kernel(const bf16* __restrict__ A,
                 const bf16* __restrict__ Wt,
                 const float* __restrict__ bias,
                 const float* __restrict__ resid,
                 const float* __restrict__ gam,
                 const float* __restrict__ bet,
                 void* __restrict__ Cv,
                 int N) {
    extern __shared__ bf16 sm[];
    bf16* As = sm;                 // [128][GS]
    bf16* Ws = sm + 128 * GS;      // [128][GS]

    const int tid  = threadIdx.x;
    const int lane = tid & 31;
    const int warp = tid >> 5;
    const int warpM = warp >> 2;        // 0..1
    const int warpN = warp & 3;         // 0..3
    const int gid = lane >> 2;          // 0..7
    const int tig = lane & 3;           // 0..3

    const long rowBase = (long)blockIdx.y * 128;
    const int  colBase = blockIdx.x * 128;
    const int  K = KT;

    float cc[4][4][4];
    #pragma unroll
    for (int mi = 0; mi < 4; mi++)
        #pragma unroll
        for (int ni = 0; ni < 4; ni++)
            #pragma unroll
            for (int e = 0; e < 4; e++) cc[mi][ni][e] = 0.f;

    // loader mapping: 2 threads per row, 8 x 16B chunks each
    const int ld_row = tid >> 1;               // 0..127
    const int ld_c0  = (tid & 1) * 64;         // half-offset 0 or 64

    // ldmatrix lane-address components
    const int a_r = (lane & 7) + ((lane >> 3) & 1) * 8;
    const int a_k = (lane >> 4) * 8;
    const int b_n = (lane & 7) + (lane >> 4) * 8;
    const int b_k = ((lane >> 3) & 1) * 8;

    constexpr int NCHUNK = KT / 128;
    #pragma unroll
    for (int kc = 0; kc < NCHUNK; kc++) {
        if (kc > 0) __syncthreads();           // everyone done reading previous chunk
        const int k0 = kc * 128;
        // issue the whole 128-k panel (8 cp.async each for A and W per thread)
        #pragma unroll
        for (int j = 0; j < 8; j++) {
            int c = ld_c0 + j * 8;
            cp_async16(&As[ld_row * GS + c], A  + (rowBase + ld_row) * K + k0 + c);
        }
        #pragma unroll
        for (int j = 0; j < 8; j++) {
            int c = ld_c0 + j * 8;
            cp_async16(&Ws[ld_row * GS + c], Wt + (long)(colBase + ld_row) * K + k0 + c);
        }
        cp_commit();
        cp_wait<0>();
        __syncthreads();

        // barrier-free compute: 8 k16 steps
        #pragma unroll
        for (int ks = 0; ks < 8; ks++) {
            const int kk = ks * 16;
            uint32_t af[4][4];
            uint32_t bf[4][2];
            #pragma unroll
            for (int mi = 0; mi < 4; mi++)
                ldsm_x4(af[mi], As + (warpM * 64 + mi * 16 + a_r) * GS + kk + a_k);
            #pragma unroll
            for (int np = 0; np < 2; np++) {
                uint32_t r4[4];
                ldsm_x4(r4, Ws + (warpN * 32 + np * 16 + b_n) * GS + kk + b_k);
                bf[2 * np][0] = r4[0]; bf[2 * np][1] = r4[1];
                bf[2 * np + 1][0] = r4[2]; bf[2 * np + 1][1] = r4[3];
            }
            #pragma unroll
            for (int mi = 0; mi < 4; mi++)
                #pragma unroll
                for (int ni = 0; ni < 4; ni++)
                    mma_bf16(cc[mi][ni], af[mi], bf[ni]);
        }
    }

    if (MODE == 1) {
        // fused: x2 = resid + proj_out (+bias), write fp32 g_x2;
        // then LayerNorm(x2) over full 128-col rows -> bf16 g_xw.
        __syncthreads();                 // all warps done with smem tiles
        float* red = (float*)sm;         // [128][2] row sums
        if (tid < 128) { red[2 * tid] = 0.f; red[2 * tid + 1] = 0.f; }
        __syncthreads();

        long orows[4][2];
        float* C = (float*)Cv;
        #pragma unroll
        for (int mi = 0; mi < 4; mi++) {
            #pragma unroll
            for (int half = 0; half < 2; half++) {
                int rloc = warpM * 64 + mi * 16 + gid + half * 8;
                long orow = win_to_spatial(rowBase + rloc);
                orows[mi][half] = orow;
                float s = 0.f, sq = 0.f;
                #pragma unroll
                for (int ni = 0; ni < 4; ni++) {
                    int col = warpN * 32 + ni * 8 + 2 * tig;
                    const float2 r = *(const float2*)(resid + orow * CDIM + col);
                    float v0 = cc[mi][ni][half * 2 + 0] + bias[col]     + r.x;
                    float v1 = cc[mi][ni][half * 2 + 1] + bias[col + 1] + r.y;
                    cc[mi][ni][half * 2 + 0] = v0;
                    cc[mi][ni][half * 2 + 1] = v1;
                    *(float2*)(C + orow * CDIM + col) = make_float2(v0, v1);
                    s += v0 + v1; sq += v0 * v0 + v1 * v1;
                }
                s  += __shfl_xor_sync(0xffffffffu, s, 1);
                sq += __shfl_xor_sync(0xffffffffu, sq, 1);
                s  += __shfl_xor_sync(0xffffffffu, s, 2);
                sq += __shfl_xor_sync(0xffffffffu, sq, 2);
                if (tig == 0) {
                    atomicAdd(&red[2 * rloc],     s);
                    atomicAdd(&red[2 * rloc + 1], sq);
                }
            }
        }
        __syncthreads();
        #pragma unroll
        for (int mi = 0; mi < 4; mi++) {
            #pragma unroll
            for (int half = 0; half < 2; half++) {
                int rloc = warpM * 64 + mi * 16 + gid + half * 8;
                long orow = orows[mi][half];
                float mean = red[2 * rloc] * (1.0f / CDIM);
                float var  = red[2 * rloc + 1] * (1.0f / CDIM) - mean * mean;
                float rstd = rsqrtf(var + 1e-5f);
                #pragma unroll
                for (int ni = 0; ni < 4; ni++) {
                    int col = warpN * 32 + ni * 8 + 2 * tig;
                    float v0 = cc[mi][ni][half * 2 + 0];
                    float v1 = cc[mi][ni][half * 2 + 1];
                    float y0 = (v0 - mean) * rstd * gam[col]     + bet[col];
                    float y1 = (v1 - mean) * rstd * gam[col + 1] + bet[col + 1];
                    bf162 p = __float22bfloat162_rn(make_float2(y0, y1));
                    *(bf162*)(g_xw + orow * CDIM + col) = p;
                }
            }
        }
        return;
    }

    // epilogue (MODE 0/2/3)
    #pragma unroll
    for (int mi = 0; mi < 4; mi++) {
        #pragma unroll
        for (int half = 0; half < 2; half++) {
            long row = rowBase + warpM * 64 + mi * 16 + gid + half * 8;
            #pragma unroll
            for (int ni = 0; ni < 4; ni++) {
                int col = colBase + warpN * 32 + ni * 8 + 2 * tig;
                float v0 = cc[mi][ni][half * 2 + 0] + bias[col];
                float v1 = cc[mi][ni][half * 2 + 1] + bias[col + 1];
                if (MODE == 0) {
                    if (col < CDIM) { v0 *= 0.17677669529663687f; v1 *= 0.17677669529663687f; }
                }
                if (MODE == 2) {
                    v0 = 0.5f * v0 * (1.0f + erff(v0 * 0.70710678118654752f));
                    v1 = 0.5f * v1 * (1.0f + erff(v1 * 0.70710678118654752f));
                }
                if (MODE == 3) {
                    float* C = (float*)Cv;
                    const float2 r = *(const float2*)(resid + row * CDIM + col);
                    *(float2*)(C + row * CDIM + col) = make_float2(v0 + r.x, v1 + r.y);
                } else {
                    bf16* C = (bf16*)Cv;
                    bf162 p = __float22bfloat162_rn(make_float2(v0, v1));
                    *(bf162*)(C + row * (long)N + col) = p;
                }
            }
        }
    }
}

// ---------------------------------------------------------------------------
// BF16 tensor-core window attention (unchanged)
// ---------------------------------------------------------------------------
#define AQS 40
#define PSS 120
#define NPAD 112
__global__ __launch_bounds__(128)
void attn_kernel() {
    extern __shared__ bf16 asm_[];
    bf16* qs  = asm_;                          // [128][40]
    bf16* ks  = qs  + 128 * AQS;               // [112][40]
    bf16* vsr = ks  + NPAD * AQS;              // [112][40]
    bf16* ps  = vsr + NPAD * AQS;              // [128][120]

    const int w = blockIdx.x;
    const int h = blockIdx.y;
    const int tid  = threadIdx.x;
    const int warp = tid >> 5;
    const int lane = tid & 31;
    const int gid = lane >> 2;
    const int tig = lane & 3;

    const bf16* base = g_qkv + (size_t)w * NTOK * QKVN + h * HD;

    for (int i = tid; i < NTOK * 4; i += 128) {
        int m = i >> 2, c = (i & 3) * 8;
        *(uint4*)&qs [m * AQS + c] = *(const uint4*)(base + m * QKVN + c);
        *(uint4*)&ks [m * AQS + c] = *(const uint4*)(base + m * QKVN + CDIM + c);
        *(uint4*)&vsr[m * AQS + c] = *(const uint4*)(base + m * QKVN + 2 * CDIM + c);
    }
    const uint4 z4 = make_uint4(0, 0, 0, 0);
    for (int i = tid; i < 30 * 4; i += 128) {
        int m = 98 + (i >> 2), c = (i & 3) * 8;
        *(uint4*)&qs[m * AQS + c] = z4;
        if (m < NPAD) {
            *(uint4*)&ks [m * AQS + c] = z4;
            *(uint4*)&vsr[m * AQS + c] = z4;
        }
    }
    __syncthreads();

    const int a_r = (lane & 7) + ((lane >> 3) & 1) * 8;
    const int a_k = (lane >> 4) * 8;
    const int b_n = (lane & 7) + (lane >> 4) * 8;
    const int b_k = ((lane >> 3) & 1) * 8;
    const int t_r = (lane & 7) + ((lane >> 3) & 1) * 8;
    const int t_c = (lane >> 4) * 8;

    float cc[2][14][4];
    #pragma unroll
    for (int mi = 0; mi < 2; mi++)
        #pragma unroll
        for (int ni = 0; ni < 14; ni++)
            #pragma unroll
            for (int e = 0; e < 4; e++) cc[mi][ni][e] = 0.f;

    #pragma unroll
    for (int ksx = 0; ksx < 2; ksx++) {
        const int kk = ksx * 16;
        uint32_t af[2][4];
        #pragma unroll
        for (int mi = 0; mi < 2; mi++)
            ldsm_x4(af[mi], qs + (warp * 32 + mi * 16 + a_r) * AQS + kk + a_k);
        #pragma unroll
        for (int np = 0; np < 7; np++) {
            uint32_t r4[4];
            ldsm_x4(r4, ks + (np * 16 + b_n) * AQS + kk + b_k);
            uint32_t b0[2] = { r4[0], r4[1] };
            uint32_t b1[2] = { r4[2], r4[3] };
            mma_bf16(cc[0][2 * np],     af[0], b0);
            mma_bf16(cc[1][2 * np],     af[1], b0);
            mma_bf16(cc[0][2 * np + 1], af[0], b1);
            mma_bf16(cc[1][2 * np + 1], af[1], b1);
        }
    }

    float rsum[2][2] = {{0.f, 0.f}, {0.f, 0.f}};
    const float* gb = g_bias + h * NTOK * NTOK;
    #pragma unroll
    for (int mi = 0; mi < 2; mi++) {
        int r0 = warp * 32 + mi * 16 + gid;
        int r1 = r0 + 8;
        const float* b0p = gb + (r0 < NTOK ? r0 : NTOK - 1) * NTOK;
        const float* b1p = gb + (r1 < NTOK ? r1 : NTOK - 1) * NTOK;
        #pragma unroll
        for (int ni = 0; ni < 14; ni++) {
            int c0 = ni * 8 + 2 * tig;
            int c1 = c0 + 1;
            int cc0 = c0 < NTOK ? c0 : NTOK - 1;
            int cc1 = c1 < NTOK ? c1 : NTOK - 1;
            float e;
            e = (c0 < NTOK) ? __expf(cc[mi][ni][0] + b0p[cc0]) : 0.f; cc[mi][ni][0] = e; rsum[mi][0] += e;
            e = (c1 < NTOK) ? __expf(cc[mi][ni][1] + b0p[cc1]) : 0.f; cc[mi][ni][1] = e; rsum[mi][0] += e;
            e = (c0 < NTOK) ? __expf(cc[mi][ni][2] + b1p[cc0]) : 0.f; cc[mi][ni][2] = e; rsum[mi][1] += e;
            e = (c1 < NTOK) ? __expf(cc[mi][ni][3] + b1p[cc1]) : 0.f; cc[mi][ni][3] = e; rsum[mi][1] += e;
        }
    }
    float inv[2][2];
    #pragma unroll
    for (int mi = 0; mi < 2; mi++)
        #pragma unroll
        for (int hf = 0; hf < 2; hf++) {
            float s = rsum[mi][hf];
            s += __shfl_xor_sync(0xffffffffu, s, 1);
            s += __shfl_xor_sync(0xffffffffu, s, 2);
            inv[mi][hf] = 1.0f / s;
        }

    #pragma unroll
    for (int mi = 0; mi < 2; mi++) {
        int r0 = warp * 32 + mi * 16 + gid;
        #pragma unroll
        for (int ni = 0; ni < 14; ni++) {
            int col = ni * 8 + 2 * tig;
            bf162 p0 = __float22bfloat162_rn(
                make_float2(cc[mi][ni][0] * inv[mi][0], cc[mi][ni][1] * inv[mi][0]));
            bf162 p1 = __float22bfloat162_rn(
                make_float2(cc[mi][ni][2] * inv[mi][1], cc[mi][ni][3] * inv[mi][1]));
            *(bf162*)&ps[r0 * PSS + col]       = p0;
            *(bf162*)&ps[(r0 + 8) * PSS + col] = p1;
        }
    }
    __syncwarp();

    float oo[2][4][4];
    #pragma unroll
    for (int mi = 0; mi < 2; mi++)
        #pragma unroll
        for (int ni = 0; ni < 4; ni++)
            #pragma unroll
            for (int e = 0; e < 4; e++) oo[mi][ni][e] = 0.f;

    #pragma unroll
    for (int k2 = 0; k2 < 7; k2++) {
        const int kk = k2 * 16;
        uint32_t af[2][4];
        #pragma unroll
        for (int mi = 0; mi < 2; mi++)
            ldsm_x4(af[mi], ps + (warp * 32 + mi * 16 + a_r) * PSS + kk + a_k);
        #pragma unroll
        for (int np = 0; np < 2; np++) {
            int n0 = np * 16;
            uint32_t r4[4];
            ldsm_x4_t(r4, vsr + (kk + t_r) * AQS + n0 + t_c);
            uint32_t b0[2] = { r4[0], r4[1] };
            uint32_t b1[2] = { r4[2], r4[3] };
            mma_bf16(oo[0][2 * np],     af[0], b0);
            mma_bf16(oo[1][2 * np],     af[1], b0);
            mma_bf16(oo[0][2 * np + 1], af[0], b1);
            mma_bf16(oo[1][2 * np + 1], af[1], b1);
        }
    }

    #pragma unroll
    for (int mi = 0; mi < 2; mi++) {
        #pragma unroll
        for (int hf = 0; hf < 2; hf++) {
            int row = warp * 32 + mi * 16 + gid + hf * 8;
            if (row < NTOK) {
                bf16* op = g_attn + ((size_t)w * NTOK + row) * CDIM + h * HD;
                #pragma unroll
                for (int ni = 0; ni < 4; ni++) {
                    int col = ni * 8 + 2 * tig;
                    bf162 p = __float22bfloat162_rn(
                        make_float2(oo[mi][ni][hf * 2], oo[mi][ni][hf * 2 + 1]));
                    *(bf162*)(op + col) = p;
                }
            }
        }
    }
}

// ---------------------------------------------------------------------------
// launcher
// ---------------------------------------------------------------------------
extern "C" void kernel_launch(void* const* d_in, const int* in_sizes, int n_in,
                              void* d_out, int out_size) {
    const float* x          = (const float*)d_in[0];
    const float* norm1_w    = (const float*)d_in[1];
    const float* norm1_b    = (const float*)d_in[2];
    const float* qkv_w      = (const float*)d_in[3];
    const float* qkv_b      = (const float*)d_in[4];
    const float* bias_table = (const float*)d_in[5];
    const float* proj_w     = (const float*)d_in[6];
    const float* proj_b     = (const float*)d_in[7];
    const float* norm2_w    = (const float*)d_in[8];
    const float* norm2_b    = (const float*)d_in[9];
    const float* fc1_w      = (const float*)d_in[10];
    const float* fc1_b      = (const float*)d_in[11];
    const float* fc2_w      = (const float*)d_in[12];
    const float* fc2_b      = (const float*)d_in[13];
    const int*   rel_index  = (const int*)d_in[14];
    float* out = (float*)d_out;

    bf16 *p_xw, *p_qkv, *p_attn, *p_h;
    bf16 *p_wq, *p_wp, *p_w1, *p_w2;
    float *p_x2;
    cudaGetSymbolAddress((void**)&p_xw,   g_xw);
    cudaGetSymbolAddress((void**)&p_qkv,  g_qkv);
    cudaGetSymbolAddress((void**)&p_attn, g_attn);
    cudaGetSymbolAddress((void**)&p_x2,   g_x2);
    cudaGetSymbolAddress((void**)&p_h,    g_h);
    cudaGetSymbolAddress((void**)&p_wq,   g_wq);
    cudaGetSymbolAddress((void**)&p_wp,   g_wp);
    cudaGetSymbolAddress((void**)&p_w1,   g_w1);
    cudaGetSymbolAddress((void**)&p_w2,   g_w2);

    const int GEMM_SMEM = 2 * 128 * GS * (int)sizeof(bf16);  // 69632
    const int ATTN_SMEM = (128 * AQS + 2 * NPAD * AQS + 128 * PSS) * (int)sizeof(bf16);
    cudaFuncSetAttribute((const void*)gemm_kernel<0,128>, cudaFuncAttributeMaxDynamicSharedMemorySize, GEMM_SMEM);
    cudaFuncSetAttribute((const void*)gemm_kernel<1,128>, cudaFuncAttributeMaxDynamicSharedMemorySize, GEMM_SMEM);
    cudaFuncSetAttribute((const void*)gemm_kernel<2,128>, cudaFuncAttributeMaxDynamicSharedMemorySize, GEMM_SMEM);
    cudaFuncSetAttribute((const void*)gemm_kernel<3,512>, cudaFuncAttributeMaxDynamicSharedMemorySize, GEMM_SMEM);
    cudaFuncSetAttribute((const void*)attn_kernel,        cudaFuncAttributeMaxDynamicSharedMemorySize, ATTN_SMEM);

    // 0) weight conversion + bias gather
    cvt_weights_kernel<<<49152 / 256, 256>>>(qkv_w, proj_w, fc1_w, fc2_w);
    bias_gather_kernel<<<dim3(NTOK, NH), NTOK>>>(bias_table, rel_index);

    // 1) LN1 + window partition (fp32 -> bf16)
    ln_kernel<true><<<TOK / 8, 256>>>(x, norm1_w, norm1_b, p_xw);

    // 2) QKV gemm (+ q scale), bf16 out
    gemm_kernel<0,128><<<dim3(QKVN / 128, TOK / 128), 256, GEMM_SMEM>>>(
        p_xw, p_wq, qkv_b, nullptr, nullptr, nullptr, p_qkv, QKVN);

    // 3) window attention (bf16 tensor cores)
    attn_kernel<<<dim3(NWIN, NH), 128, ATTN_SMEM>>>();

    // 4) proj gemm + window reverse + residual(x) -> g_x2 (fp32)  + fused LN2 -> g_xw (bf16)
    gemm_kernel<1,128><<<dim3(CDIM / 128, TOK / 128), 256, GEMM_SMEM>>>(
        p_attn, p_wp, proj_b, x, norm2_w, norm2_b, p_x2, CDIM);

    // 5) fc1 + exact GELU, bf16 out
    gemm_kernel<2,128><<<dim3(CH / 128, TOK / 128), 256, GEMM_SMEM>>>(
        p_xw, p_w1, fc1_b, nullptr, nullptr, nullptr, p_h, CH);

    // 6) fc2 + residual(g_x2) -> d_out (fp32)
    gemm_kernel<3,512><<<dim3(CDIM / 128, TOK / 128), 256, GEMM_SMEM>>>(
        p_h, p_w2, fc2_b, p_x2, nullptr, nullptr, out, CDIM);

    (void)in_sizes; (void)n_in; (void)out_size;
}

// round 7
// speedup vs baseline: 1.6300x; 1.6300x over previous
#include <cuda_runtime.h>
#include <cuda_bf16.h>
#include <math.h>
#include <stdint.h>

// ---------------------------------------------------------------------------
// Problem constants
// ---------------------------------------------------------------------------
#define TOK   50176      // 2*8*56*56
#define CDIM  128
#define CH    512
#define NWIN  512        // 2 * 4*8*8
#define NTOK  98         // 2*7*7
#define NH    4
#define HD    32
#define QKVN  384

typedef __nv_bfloat16  bf16;
typedef __nv_bfloat162 bf162;

// ---------------------------------------------------------------------------
// Scratch (device globals: allocation-free, graph-capture safe)
// ---------------------------------------------------------------------------
__device__ bf16  g_xw  [(size_t)TOK * CDIM];   // LN1 out (window order) / LN2 out (spatial)
__device__ bf16  g_qkv [(size_t)TOK * QKVN];   // qkv, window order
__device__ bf16  g_attn[(size_t)TOK * CDIM];   // attention out, window order
__device__ float g_x2  [(size_t)TOK * CDIM];   // x + proj (spatial, fp32)
__device__ bf16  g_h   [(size_t)TOK * CH];     // fc1 output
__device__ float g_bias[NH * NTOK * NTOK];     // gathered attention bias (fp32)
// bf16 weights
__device__ bf16  g_wq[QKVN * CDIM];
__device__ bf16  g_wp[CDIM * CDIM];
__device__ bf16  g_w1[CH * CDIM];
__device__ bf16  g_w2[CDIM * CH];

// ---------------------------------------------------------------------------
// index helpers
// ---------------------------------------------------------------------------
__device__ __forceinline__ long win_to_spatial(long row) {
    int w = (int)(row / NTOK);
    int n = (int)(row % NTOK);
    int b   = w >> 8;
    int rem = w & 255;
    int wdi = rem >> 6, whi = (rem >> 3) & 7, wwi = rem & 7;
    int zd = n / 49; int r2 = n % 49; int zh = r2 / 7, zw = r2 % 7;
    int d  = wdi * 2 + zd;
    int hh = whi * 7 + zh;
    int xx = wwi * 7 + zw;
    return (((long)(b * 8 + d) * 56) + hh) * 56 + xx;
}

__device__ __forceinline__ long spatial_to_win(long t) {
    int b  = (int)(t / 25088);
    int r  = (int)(t % 25088);
    int d  = r / 3136; r %= 3136;
    int hh = r / 56;
    int xx = r % 56;
    int widx = ((b * 4 + (d >> 1)) * 8 + hh / 7) * 8 + xx / 7;
    int n    = ((d & 1) * 7 + hh % 7) * 7 + xx % 7;
    return (long)widx * NTOK + n;
}

// ---------------------------------------------------------------------------
// async copy + ldmatrix + mma helpers
// ---------------------------------------------------------------------------
__device__ __forceinline__ void cp_async16(bf16* smem_dst, const bf16* gmem_src) {
    uint32_t s = (uint32_t)__cvta_generic_to_shared(smem_dst);
    asm volatile("cp.async.cg.shared.global [%0], [%1], 16;\n" :: "r"(s), "l"(gmem_src));
}
__device__ __forceinline__ void cp_commit() { asm volatile("cp.async.commit_group;\n"); }
template<int N>
__device__ __forceinline__ void cp_wait() { asm volatile("cp.async.wait_group %0;\n" :: "n"(N)); }

__device__ __forceinline__ void ldsm_x4(uint32_t r[4], const bf16* p) {
    uint32_t a = (uint32_t)__cvta_generic_to_shared(p);
    asm volatile("ldmatrix.sync.aligned.m8n8.x4.shared.b16 {%0,%1,%2,%3}, [%4];\n"
                 : "=r"(r[0]), "=r"(r[1]), "=r"(r[2]), "=r"(r[3]) : "r"(a));
}
__device__ __forceinline__ void ldsm_x4_t(uint32_t r[4], const bf16* p) {
    uint32_t a = (uint32_t)__cvta_generic_to_shared(p);
    asm volatile("ldmatrix.sync.aligned.m8n8.x4.trans.shared.b16 {%0,%1,%2,%3}, [%4];\n"
                 : "=r"(r[0]), "=r"(r[1]), "=r"(r[2]), "=r"(r[3]) : "r"(a));
}
__device__ __forceinline__ void mma_bf16(float c[4], const uint32_t a[4], const uint32_t b[2]) {
    asm volatile(
        "mma.sync.aligned.m16n8k16.row.col.f32.bf16.bf16.f32 "
        "{%0,%1,%2,%3}, {%4,%5,%6,%7}, {%8,%9}, {%0,%1,%2,%3};\n"
        : "+f"(c[0]), "+f"(c[1]), "+f"(c[2]), "+f"(c[3])
        : "r"(a[0]), "r"(a[1]), "r"(a[2]), "r"(a[3]), "r"(b[0]), "r"(b[1]));
}

// ---------------------------------------------------------------------------
// fused weight conversion fp32 -> bf16 (float4 granularity)
// ---------------------------------------------------------------------------
__global__ void cvt_weights_kernel(const float* __restrict__ wq,
                                   const float* __restrict__ wp,
                                   const float* __restrict__ w1,
                                   const float* __restrict__ w2) {
    int i = blockIdx.x * blockDim.x + threadIdx.x;   // float4 index, total 49152
    const float* src; bf16* dst; int off;
    if (i < 12288)      { src = wq; dst = g_wq; off = i; }
    else if (i < 16384) { src = wp; dst = g_wp; off = i - 12288; }
    else if (i < 32768) { src = w1; dst = g_w1; off = i - 16384; }
    else                { src = w2; dst = g_w2; off = i - 32768; }
    float4 v = *(const float4*)(src + off * 4);
    bf162 p0 = __float22bfloat162_rn(make_float2(v.x, v.y));
    bf162 p1 = __float22bfloat162_rn(make_float2(v.z, v.w));
    uint2 u = make_uint2(*(uint32_t*)&p0, *(uint32_t*)&p1);
    *(uint2*)(dst + off * 4) = u;
}

// ---------------------------------------------------------------------------
// bias gather: g_bias[h][n][m] = bias_table[rel_index[n][m]][h]
// ---------------------------------------------------------------------------
__global__ void bias_gather_kernel(const float* __restrict__ bias_table,
                                   const int* __restrict__ rel_index) {
    int m = threadIdx.x;
    int n = blockIdx.x;
    int h = blockIdx.y;
    int idx = rel_index[n * NTOK + m];
    g_bias[(h * NTOK + n) * NTOK + m] = bias_table[idx * NH + h];
}

// ---------------------------------------------------------------------------
// LayerNorm over C=128 (fp32 in, bf16 out): one warp per token.
// ---------------------------------------------------------------------------
template<bool PERMUTE>
__global__ __launch_bounds__(256)
void ln_kernel(const float* __restrict__ in,
               const float* __restrict__ gam,
               const float* __restrict__ bet,
               bf16* __restrict__ out) {
    int warp = threadIdx.x >> 5;
    int lane = threadIdx.x & 31;
    long t = (long)blockIdx.x * 8 + warp;
    const float4 v = *(const float4*)(in + t * CDIM + lane * 4);
    float s  = v.x + v.y + v.z + v.w;
    float sq = v.x * v.x + v.y * v.y + v.z * v.z + v.w * v.w;
    #pragma unroll
    for (int o = 16; o; o >>= 1) {
        s  += __shfl_xor_sync(0xffffffffu, s,  o);
        sq += __shfl_xor_sync(0xffffffffu, sq, o);
    }
    float mean = s * (1.0f / CDIM);
    float var  = sq * (1.0f / CDIM) - mean * mean;
    float rstd = rsqrtf(var + 1e-5f);
    const float4 g = *(const float4*)(gam + lane * 4);
    const float4 b = *(const float4*)(bet + lane * 4);
    bf162 p0 = __float22bfloat162_rn(make_float2((v.x - mean) * rstd * g.x + b.x,
                                                 (v.y - mean) * rstd * g.y + b.y));
    bf162 p1 = __float22bfloat162_rn(make_float2((v.z - mean) * rstd * g.z + b.z,
                                                 (v.w - mean) * rstd * g.w + b.w));
    long orow = PERMUTE ? spatial_to_win(t) : t;
    uint2 u = make_uint2(*(uint32_t*)&p0, *(uint32_t*)&p1);
    *(uint2*)(out + orow * CDIM + lane * 4) = u;
}

// ---------------------------------------------------------------------------
// BF16 tensor-core GEMM v5: C[M,N] = A[M,K] @ W[N,K]^T (+ epilogue)
// Block 128x128, BK=64, 3-stage cp.async pipeline, one sync per 64-k iter
// (2 syncs total for K=128), prefetch distance 2 keeps load/compute overlap.
// 256 threads (8 warps: 2x4), warp tile 64x32, m16n8k16 + ldmatrix.x4.
// MODE 0: qkv  -> +bias; scale q-part; bf16 out [M,384]
// MODE 1: proj -> +bias; permute; += resid(x); fp32 g_x2  AND fused LN2 -> bf16 g_xw
// MODE 2: fc1  -> +bias; exact GELU; bf16 out [M,512]
// MODE 3: fc2  -> +bias; += resid(g_x2); fp32 out d_out
// ---------------------------------------------------------------------------
#define GS 72                  // smem row stride (halves): 64 + 8 pad
#define G_STAGE (256 * GS)     // As(128)+Ws(128) rows per stage
template<int MODE, int KT>
__global__ __launch_bounds__(256, 2)
void gemm_kernel(const bf16* __restrict__ A,
                 const bf16* __restrict__ Wt,
                 const float* __restrict__ bias,
                 const float* __restrict__ resid,
                 const float* __restrict__ gam,
                 const float* __restrict__ bet,
                 void* __restrict__ Cv,
                 int N) {
    extern __shared__ bf16 sm[];
    bf16* Asb[3] = { sm, sm + G_STAGE, sm + 2 * G_STAGE };
    bf16* Wsb[3] = { sm + 128 * GS, sm + G_STAGE + 128 * GS, sm + 2 * G_STAGE + 128 * GS };

    const int tid  = threadIdx.x;
    const int lane = tid & 31;
    const int warp = tid >> 5;
    const int warpM = warp >> 2;        // 0..1
    const int warpN = warp & 3;         // 0..3
    const int gid = lane >> 2;          // 0..7
    const int tig = lane & 3;           // 0..3

    const long rowBase = (long)blockIdx.y * 128;
    const int  colBase = blockIdx.x * 128;
    const int  K = KT;

    float cc[4][4][4];
    #pragma unroll
    for (int mi = 0; mi < 4; mi++)
        #pragma unroll
        for (int ni = 0; ni < 4; ni++)
            #pragma unroll
            for (int e = 0; e < 4; e++) cc[mi][ni][e] = 0.f;

    // loader: 2 threads per row, 4 x 16B chunks each (64 halves per row)
    const int ld_row = tid >> 1;               // 0..127
    const int ld_c0  = (tid & 1) * 32;         // half-offset 0 or 32

    auto load_tile = [&](int buf, int k0) {
        #pragma unroll
        for (int j = 0; j < 4; j++) {
            int c = ld_c0 + j * 8;
            cp_async16(&Asb[buf][ld_row * GS + c], A  + (rowBase + ld_row) * K + k0 + c);
        }
        #pragma unroll
        for (int j = 0; j < 4; j++) {
            int c = ld_c0 + j * 8;
            cp_async16(&Wsb[buf][ld_row * GS + c], Wt + (long)(colBase + ld_row) * K + k0 + c);
        }
    };

    constexpr int nk = KT / 64;
    load_tile(0, 0);  cp_commit();
    if (nk > 1) { load_tile(1, 64); cp_commit(); }

    // ldmatrix lane-address components
    const int a_r = (lane & 7) + ((lane >> 3) & 1) * 8;
    const int a_k = (lane >> 4) * 8;
    const int b_n = (lane & 7) + (lane >> 4) * 8;
    const int b_k = ((lane >> 3) & 1) * 8;

    #pragma unroll
    for (int it = 0; it < nk; it++) {
        if (it + 1 < nk) cp_wait<1>(); else cp_wait<0>();
        __syncthreads();
        // prefetch stage it+2 (safe: stage (it+2)%3 == (it-1)%3, already consumed)
        if (it + 2 < nk) { load_tile((it + 2) % 3, (it + 2) * 64); cp_commit(); }

        const bf16* As = Asb[it % 3];
        const bf16* Ws = Wsb[it % 3];
        #pragma unroll
        for (int ks = 0; ks < 4; ks++) {
            const int kk = ks * 16;
            uint32_t af[4][4];
            uint32_t bf[4][2];
            #pragma unroll
            for (int mi = 0; mi < 4; mi++)
                ldsm_x4(af[mi], As + (warpM * 64 + mi * 16 + a_r) * GS + kk + a_k);
            #pragma unroll
            for (int np = 0; np < 2; np++) {
                uint32_t r4[4];
                ldsm_x4(r4, Ws + (warpN * 32 + np * 16 + b_n) * GS + kk + b_k);
                bf[2 * np][0] = r4[0]; bf[2 * np][1] = r4[1];
                bf[2 * np + 1][0] = r4[2]; bf[2 * np + 1][1] = r4[3];
            }
            #pragma unroll
            for (int mi = 0; mi < 4; mi++)
                #pragma unroll
                for (int ni = 0; ni < 4; ni++)
                    mma_bf16(cc[mi][ni], af[mi], bf[ni]);
        }
    }

    if (MODE == 1) {
        // fused: x2 = resid + proj_out (+bias), write fp32 g_x2;
        // then LayerNorm(x2) over full 128-col rows -> bf16 g_xw.
        __syncthreads();                 // all warps done with smem tiles
        float* red = (float*)sm;         // [128][2] row sums
        if (tid < 128) { red[2 * tid] = 0.f; red[2 * tid + 1] = 0.f; }
        __syncthreads();

        long orows[4][2];
        float* C = (float*)Cv;
        #pragma unroll
        for (int mi = 0; mi < 4; mi++) {
            #pragma unroll
            for (int half = 0; half < 2; half++) {
                int rloc = warpM * 64 + mi * 16 + gid + half * 8;
                long orow = win_to_spatial(rowBase + rloc);
                orows[mi][half] = orow;
                float s = 0.f, sq = 0.f;
                #pragma unroll
                for (int ni = 0; ni < 4; ni++) {
                    int col = warpN * 32 + ni * 8 + 2 * tig;
                    const float2 r = *(const float2*)(resid + orow * CDIM + col);
                    float v0 = cc[mi][ni][half * 2 + 0] + bias[col]     + r.x;
                    float v1 = cc[mi][ni][half * 2 + 1] + bias[col + 1] + r.y;
                    cc[mi][ni][half * 2 + 0] = v0;
                    cc[mi][ni][half * 2 + 1] = v1;
                    *(float2*)(C + orow * CDIM + col) = make_float2(v0, v1);
                    s += v0 + v1; sq += v0 * v0 + v1 * v1;
                }
                s  += __shfl_xor_sync(0xffffffffu, s, 1);
                sq += __shfl_xor_sync(0xffffffffu, sq, 1);
                s  += __shfl_xor_sync(0xffffffffu, s, 2);
                sq += __shfl_xor_sync(0xffffffffu, sq, 2);
                if (tig == 0) {
                    atomicAdd(&red[2 * rloc],     s);
                    atomicAdd(&red[2 * rloc + 1], sq);
                }
            }
        }
        __syncthreads();
        #pragma unroll
        for (int mi = 0; mi < 4; mi++) {
            #pragma unroll
            for (int half = 0; half < 2; half++) {
                int rloc = warpM * 64 + mi * 16 + gid + half * 8;
                long orow = orows[mi][half];
                float mean = red[2 * rloc] * (1.0f / CDIM);
                float var  = red[2 * rloc + 1] * (1.0f / CDIM) - mean * mean;
                float rstd = rsqrtf(var + 1e-5f);
                #pragma unroll
                for (int ni = 0; ni < 4; ni++) {
                    int col = warpN * 32 + ni * 8 + 2 * tig;
                    float v0 = cc[mi][ni][half * 2 + 0];
                    float v1 = cc[mi][ni][half * 2 + 1];
                    float y0 = (v0 - mean) * rstd * gam[col]     + bet[col];
                    float y1 = (v1 - mean) * rstd * gam[col + 1] + bet[col + 1];
                    bf162 p = __float22bfloat162_rn(make_float2(y0, y1));
                    *(bf162*)(g_xw + orow * CDIM + col) = p;
                }
            }
        }
        return;
    }

    // epilogue (MODE 0/2/3)
    #pragma unroll
    for (int mi = 0; mi < 4; mi++) {
        #pragma unroll
        for (int half = 0; half < 2; half++) {
            long row = rowBase + warpM * 64 + mi * 16 + gid + half * 8;
            #pragma unroll
            for (int ni = 0; ni < 4; ni++) {
                int col = colBase + warpN * 32 + ni * 8 + 2 * tig;
                float v0 = cc[mi][ni][half * 2 + 0] + bias[col];
                float v1 = cc[mi][ni][half * 2 + 1] + bias[col + 1];
                if (MODE == 0) {
                    if (col < CDIM) { v0 *= 0.17677669529663687f; v1 *= 0.17677669529663687f; }
                }
                if (MODE == 2) {
                    v0 = 0.5f * v0 * (1.0f + erff(v0 * 0.70710678118654752f));
                    v1 = 0.5f * v1 * (1.0f + erff(v1 * 0.70710678118654752f));
                }
                if (MODE == 3) {
                    float* C = (float*)Cv;
                    const float2 r = *(const float2*)(resid + row * CDIM + col);
                    *(float2*)(C + row * CDIM + col) = make_float2(v0 + r.x, v1 + r.y);
                } else {
                    bf16* C = (bf16*)Cv;
                    bf162 p = __float22bfloat162_rn(make_float2(v0, v1));
                    *(bf162*)(C + row * (long)N + col) = p;
                }
            }
        }
    }
}

// ---------------------------------------------------------------------------
// BF16 tensor-core window attention (unchanged from R5)
// ---------------------------------------------------------------------------
#define AQS 40
#define PSS 120
#define NPAD 112
__global__ __launch_bounds__(128)
void attn_kernel() {
    extern __shared__ bf16 asm_[];
    bf16* qs  = asm_;                          // [128][40]
    bf16* ks  = qs  + 128 * AQS;               // [112][40]
    bf16* vsr = ks  + NPAD * AQS;              // [112][40]
    bf16* ps  = vsr + NPAD * AQS;              // [128][120]

    const int w = blockIdx.x;
    const int h = blockIdx.y;
    const int tid  = threadIdx.x;
    const int warp = tid >> 5;
    const int lane = tid & 31;
    const int gid = lane >> 2;
    const int tig = lane & 3;

    const bf16* base = g_qkv + (size_t)w * NTOK * QKVN + h * HD;

    for (int i = tid; i < NTOK * 4; i += 128) {
        int m = i >> 2, c = (i & 3) * 8;
        *(uint4*)&qs [m * AQS + c] = *(const uint4*)(base + m * QKVN + c);
        *(uint4*)&ks [m * AQS + c] = *(const uint4*)(base + m * QKVN + CDIM + c);
        *(uint4*)&vsr[m * AQS + c] = *(const uint4*)(base + m * QKVN + 2 * CDIM + c);
    }
    const uint4 z4 = make_uint4(0, 0, 0, 0);
    for (int i = tid; i < 30 * 4; i += 128) {
        int m = 98 + (i >> 2), c = (i & 3) * 8;
        *(uint4*)&qs[m * AQS + c] = z4;
        if (m < NPAD) {
            *(uint4*)&ks [m * AQS + c] = z4;
            *(uint4*)&vsr[m * AQS + c] = z4;
        }
    }
    __syncthreads();

    const int a_r = (lane & 7) + ((lane >> 3) & 1) * 8;
    const int a_k = (lane >> 4) * 8;
    const int b_n = (lane & 7) + (lane >> 4) * 8;
    const int b_k = ((lane >> 3) & 1) * 8;
    const int t_r = (lane & 7) + ((lane >> 3) & 1) * 8;
    const int t_c = (lane >> 4) * 8;

    float cc[2][14][4];
    #pragma unroll
    for (int mi = 0; mi < 2; mi++)
        #pragma unroll
        for (int ni = 0; ni < 14; ni++)
            #pragma unroll
            for (int e = 0; e < 4; e++) cc[mi][ni][e] = 0.f;

    #pragma unroll
    for (int ksx = 0; ksx < 2; ksx++) {
        const int kk = ksx * 16;
        uint32_t af[2][4];
        #pragma unroll
        for (int mi = 0; mi < 2; mi++)
            ldsm_x4(af[mi], qs + (warp * 32 + mi * 16 + a_r) * AQS + kk + a_k);
        #pragma unroll
        for (int np = 0; np < 7; np++) {
            uint32_t r4[4];
            ldsm_x4(r4, ks + (np * 16 + b_n) * AQS + kk + b_k);
            uint32_t b0[2] = { r4[0], r4[1] };
            uint32_t b1[2] = { r4[2], r4[3] };
            mma_bf16(cc[0][2 * np],     af[0], b0);
            mma_bf16(cc[1][2 * np],     af[1], b0);
            mma_bf16(cc[0][2 * np + 1], af[0], b1);
            mma_bf16(cc[1][2 * np + 1], af[1], b1);
        }
    }

    float rsum[2][2] = {{0.f, 0.f}, {0.f, 0.f}};
    const float* gb = g_bias + h * NTOK * NTOK;
    #pragma unroll
    for (int mi = 0; mi < 2; mi++) {
        int r0 = warp * 32 + mi * 16 + gid;
        int r1 = r0 + 8;
        const float* b0p = gb + (r0 < NTOK ? r0 : NTOK - 1) * NTOK;
        const float* b1p = gb + (r1 < NTOK ? r1 : NTOK - 1) * NTOK;
        #pragma unroll
        for (int ni = 0; ni < 14; ni++) {
            int c0 = ni * 8 + 2 * tig;
            int c1 = c0 + 1;
            int cc0 = c0 < NTOK ? c0 : NTOK - 1;
            int cc1 = c1 < NTOK ? c1 : NTOK - 1;
            float e;
            e = (c0 < NTOK) ? __expf(cc[mi][ni][0] + b0p[cc0]) : 0.f; cc[mi][ni][0] = e; rsum[mi][0] += e;
            e = (c1 < NTOK) ? __expf(cc[mi][ni][1] + b0p[cc1]) : 0.f; cc[mi][ni][1] = e; rsum[mi][0] += e;
            e = (c0 < NTOK) ? __expf(cc[mi][ni][2] + b1p[cc0]) : 0.f; cc[mi][ni][2] = e; rsum[mi][1] += e;
            e = (c1 < NTOK) ? __expf(cc[mi][ni][3] + b1p[cc1]) : 0.f; cc[mi][ni][3] = e; rsum[mi][1] += e;
        }
    }
    float inv[2][2];
    #pragma unroll
    for (int mi = 0; mi < 2; mi++)
        #pragma unroll
        for (int hf = 0; hf < 2; hf++) {
            float s = rsum[mi][hf];
            s += __shfl_xor_sync(0xffffffffu, s, 1);
            s += __shfl_xor_sync(0xffffffffu, s, 2);
            inv[mi][hf] = 1.0f / s;
        }

    #pragma unroll
    for (int mi = 0; mi < 2; mi++) {
        int r0 = warp * 32 + mi * 16 + gid;
        #pragma unroll
        for (int ni = 0; ni < 14; ni++) {
            int col = ni * 8 + 2 * tig;
            bf162 p0 = __float22bfloat162_rn(
                make_float2(cc[mi][ni][0] * inv[mi][0], cc[mi][ni][1] * inv[mi][0]));
            bf162 p1 = __float22bfloat162_rn(
                make_float2(cc[mi][ni][2] * inv[mi][1], cc[mi][ni][3] * inv[mi][1]));
            *(bf162*)&ps[r0 * PSS + col]       = p0;
            *(bf162*)&ps[(r0 + 8) * PSS + col] = p1;
        }
    }
    __syncwarp();

    float oo[2][4][4];
    #pragma unroll
    for (int mi = 0; mi < 2; mi++)
        #pragma unroll
        for (int ni = 0; ni < 4; ni++)
            #pragma unroll
            for (int e = 0; e < 4; e++) oo[mi][ni][e] = 0.f;

    #pragma unroll
    for (int k2 = 0; k2 < 7; k2++) {
        const int kk = k2 * 16;
        uint32_t af[2][4];
        #pragma unroll
        for (int mi = 0; mi < 2; mi++)
            ldsm_x4(af[mi], ps + (warp * 32 + mi * 16 + a_r) * PSS + kk + a_k);
        #pragma unroll
        for (int np = 0; np < 2; np++) {
            int n0 = np * 16;
            uint32_t r4[4];
            ldsm_x4_t(r4, vsr + (kk + t_r) * AQS + n0 + t_c);
            uint32_t b0[2] = { r4[0], r4[1] };
            uint32_t b1[2] = { r4[2], r4[3] };
            mma_bf16(oo[0][2 * np],     af[0], b0);
            mma_bf16(oo[1][2 * np],     af[1], b0);
            mma_bf16(oo[0][2 * np + 1], af[0], b1);
            mma_bf16(oo[1][2 * np + 1], af[1], b1);
        }
    }

    #pragma unroll
    for (int mi = 0; mi < 2; mi++) {
        #pragma unroll
        for (int hf = 0; hf < 2; hf++) {
            int row = warp * 32 + mi * 16 + gid + hf * 8;
            if (row < NTOK) {
                bf16* op = g_attn + ((size_t)w * NTOK + row) * CDIM + h * HD;
                #pragma unroll
                for (int ni = 0; ni < 4; ni++) {
                    int col = ni * 8 + 2 * tig;
                    bf162 p = __float22bfloat162_rn(
                        make_float2(oo[mi][ni][hf * 2], oo[mi][ni][hf * 2 + 1]));
                    *(bf162*)(op + col) = p;
                }
            }
        }
    }
}

// ---------------------------------------------------------------------------
// launcher
// ---------------------------------------------------------------------------
extern "C" void kernel_launch(void* const* d_in, const int* in_sizes, int n_in,
                              void* d_out, int out_size) {
    const float* x          = (const float*)d_in[0];
    const float* norm1_w    = (const float*)d_in[1];
    const float* norm1_b    = (const float*)d_in[2];
    const float* qkv_w      = (const float*)d_in[3];
    const float* qkv_b      = (const float*)d_in[4];
    const float* bias_table = (const float*)d_in[5];
    const float* proj_w     = (const float*)d_in[6];
    const float* proj_b     = (const float*)d_in[7];
    const float* norm2_w    = (const float*)d_in[8];
    const float* norm2_b    = (const float*)d_in[9];
    const float* fc1_w      = (const float*)d_in[10];
    const float* fc1_b      = (const float*)d_in[11];
    const float* fc2_w      = (const float*)d_in[12];
    const float* fc2_b      = (const float*)d_in[13];
    const int*   rel_index  = (const int*)d_in[14];
    float* out = (float*)d_out;

    bf16 *p_xw, *p_qkv, *p_attn, *p_h;
    bf16 *p_wq, *p_wp, *p_w1, *p_w2;
    float *p_x2;
    cudaGetSymbolAddress((void**)&p_xw,   g_xw);
    cudaGetSymbolAddress((void**)&p_qkv,  g_qkv);
    cudaGetSymbolAddress((void**)&p_attn, g_attn);
    cudaGetSymbolAddress((void**)&p_x2,   g_x2);
    cudaGetSymbolAddress((void**)&p_h,    g_h);
    cudaGetSymbolAddress((void**)&p_wq,   g_wq);
    cudaGetSymbolAddress((void**)&p_wp,   g_wp);
    cudaGetSymbolAddress((void**)&p_w1,   g_w1);
    cudaGetSymbolAddress((void**)&p_w2,   g_w2);

    const int GEMM_SMEM = 3 * G_STAGE * (int)sizeof(bf16);   // 110592
    const int ATTN_SMEM = (128 * AQS + 2 * NPAD * AQS + 128 * PSS) * (int)sizeof(bf16);
    cudaFuncSetAttribute((const void*)gemm_kernel<0,128>, cudaFuncAttributeMaxDynamicSharedMemorySize, GEMM_SMEM);
    cudaFuncSetAttribute((const void*)gemm_kernel<1,128>, cudaFuncAttributeMaxDynamicSharedMemorySize, GEMM_SMEM);
    cudaFuncSetAttribute((const void*)gemm_kernel<2,128>, cudaFuncAttributeMaxDynamicSharedMemorySize, GEMM_SMEM);
    cudaFuncSetAttribute((const void*)gemm_kernel<3,512>, cudaFuncAttributeMaxDynamicSharedMemorySize, GEMM_SMEM);
    cudaFuncSetAttribute((const void*)attn_kernel,        cudaFuncAttributeMaxDynamicSharedMemorySize, ATTN_SMEM);

    // 0) weight conversion + bias gather
    cvt_weights_kernel<<<49152 / 256, 256>>>(qkv_w, proj_w, fc1_w, fc2_w);
    bias_gather_kernel<<<dim3(NTOK, NH), NTOK>>>(bias_table, rel_index);

    // 1) LN1 + window partition (fp32 -> bf16)
    ln_kernel<true><<<TOK / 8, 256>>>(x, norm1_w, norm1_b, p_xw);

    // 2) QKV gemm (+ q scale), bf16 out
    gemm_kernel<0,128><<<dim3(QKVN / 128, TOK / 128), 256, GEMM_SMEM>>>(
        p_xw, p_wq, qkv_b, nullptr, nullptr, nullptr, p_qkv, QKVN);

    // 3) window attention (bf16 tensor cores)
    attn_kernel<<<dim3(NWIN, NH), 128, ATTN_SMEM>>>();

    // 4) proj gemm + window reverse + residual(x) -> g_x2 (fp32)  + fused LN2 -> g_xw (bf16)
    gemm_kernel<1,128><<<dim3(CDIM / 128, TOK / 128), 256, GEMM_SMEM>>>(
        p_attn, p_wp, proj_b, x, norm2_w, norm2_b, p_x2, CDIM);

    // 5) fc1 + exact GELU, bf16 out
    gemm_kernel<2,128><<<dim3(CH / 128, TOK / 128), 256, GEMM_SMEM>>>(
        p_xw, p_w1, fc1_b, nullptr, nullptr, nullptr, p_h, CH);

    // 6) fc2 + residual(g_x2) -> d_out (fp32)
    gemm_kernel<3,512><<<dim3(CDIM / 128, TOK / 128), 256, GEMM_SMEM>>>(
        p_h, p_w2, fc2_b, p_x2, nullptr, nullptr, out, CDIM);

    (void)in_sizes; (void)n_in; (void)out_size;
}

// round 9
// speedup vs baseline: 1.7780x; 1.0908x over previous
#include <cuda_runtime.h>
#include <cuda_bf16.h>
#include <math.h>
#include <stdint.h>

// ---------------------------------------------------------------------------
// Problem constants
// ---------------------------------------------------------------------------
#define TOK   50176      // 2*8*56*56
#define CDIM  128
#define CH    512
#define NWIN  512        // 2 * 4*8*8
#define NTOK  98         // 2*7*7
#define NH    4
#define HD    32
#define QKVN  384

typedef __nv_bfloat16  bf16;
typedef __nv_bfloat162 bf162;

// ---------------------------------------------------------------------------
// Scratch (device globals: allocation-free, graph-capture safe)
// ---------------------------------------------------------------------------
__device__ bf16  g_xw  [(size_t)TOK * CDIM];   // LN1 out (window order) / LN2 out (spatial)
__device__ bf16  g_qkv [(size_t)TOK * QKVN];   // qkv, window order
__device__ bf16  g_attn[(size_t)TOK * CDIM];   // attention out, window order
__device__ float g_x2  [(size_t)TOK * CDIM];   // x + proj (spatial, fp32)
__device__ bf16  g_h   [(size_t)TOK * CH];     // fc1 output
__device__ float g_bias[NH * NTOK * NTOK];     // gathered attention bias (fp32)
// bf16 weights
__device__ bf16  g_wq[QKVN * CDIM];
__device__ bf16  g_wp[CDIM * CDIM];
__device__ bf16  g_w1[CH * CDIM];
__device__ bf16  g_w2[CDIM * CH];

// ---------------------------------------------------------------------------
// index helpers
// ---------------------------------------------------------------------------
__device__ __forceinline__ long win_to_spatial(long row) {
    int w = (int)(row / NTOK);
    int n = (int)(row % NTOK);
    int b   = w >> 8;
    int rem = w & 255;
    int wdi = rem >> 6, whi = (rem >> 3) & 7, wwi = rem & 7;
    int zd = n / 49; int r2 = n % 49; int zh = r2 / 7, zw = r2 % 7;
    int d  = wdi * 2 + zd;
    int hh = whi * 7 + zh;
    int xx = wwi * 7 + zw;
    return (((long)(b * 8 + d) * 56) + hh) * 56 + xx;
}

__device__ __forceinline__ long spatial_to_win(long t) {
    int b  = (int)(t / 25088);
    int r  = (int)(t % 25088);
    int d  = r / 3136; r %= 3136;
    int hh = r / 56;
    int xx = r % 56;
    int widx = ((b * 4 + (d >> 1)) * 8 + hh / 7) * 8 + xx / 7;
    int n    = ((d & 1) * 7 + hh % 7) * 7 + xx % 7;
    return (long)widx * NTOK + n;
}

// ---------------------------------------------------------------------------
// async copy + ldmatrix + mma helpers
// ---------------------------------------------------------------------------
__device__ __forceinline__ void cp_async16(bf16* smem_dst, const bf16* gmem_src) {
    uint32_t s = (uint32_t)__cvta_generic_to_shared(smem_dst);
    asm volatile("cp.async.cg.shared.global [%0], [%1], 16;\n" :: "r"(s), "l"(gmem_src));
}
__device__ __forceinline__ void cp_commit() { asm volatile("cp.async.commit_group;\n"); }
template<int N>
__device__ __forceinline__ void cp_wait() { asm volatile("cp.async.wait_group %0;\n" :: "n"(N)); }

__device__ __forceinline__ void ldsm_x4(uint32_t r[4], const bf16* p) {
    uint32_t a = (uint32_t)__cvta_generic_to_shared(p);
    asm volatile("ldmatrix.sync.aligned.m8n8.x4.shared.b16 {%0,%1,%2,%3}, [%4];\n"
                 : "=r"(r[0]), "=r"(r[1]), "=r"(r[2]), "=r"(r[3]) : "r"(a));
}
__device__ __forceinline__ void ldsm_x4_t(uint32_t r[4], const bf16* p) {
    uint32_t a = (uint32_t)__cvta_generic_to_shared(p);
    asm volatile("ldmatrix.sync.aligned.m8n8.x4.trans.shared.b16 {%0,%1,%2,%3}, [%4];\n"
                 : "=r"(r[0]), "=r"(r[1]), "=r"(r[2]), "=r"(r[3]) : "r"(a));
}
__device__ __forceinline__ void mma_bf16(float c[4], const uint32_t a[4], const uint32_t b[2]) {
    asm volatile(
        "mma.sync.aligned.m16n8k16.row.col.f32.bf16.bf16.f32 "
        "{%0,%1,%2,%3}, {%4,%5,%6,%7}, {%8,%9}, {%0,%1,%2,%3};\n"
        : "+f"(c[0]), "+f"(c[1]), "+f"(c[2]), "+f"(c[3])
        : "r"(a[0]), "r"(a[1]), "r"(a[2]), "r"(a[3]), "r"(b[0]), "r"(b[1]));
}

__device__ __forceinline__ uint32_t pack_bf2(float a, float b) {
    bf162 p = __float22bfloat162_rn(make_float2(a, b));
    return *(uint32_t*)&p;
}

// ---------------------------------------------------------------------------
// fused weight conversion fp32 -> bf16 (float4 granularity)
// ---------------------------------------------------------------------------
__global__ void cvt_weights_kernel(const float* __restrict__ wq,
                                   const float* __restrict__ wp,
                                   const float* __restrict__ w1,
                                   const float* __restrict__ w2) {
    int i = blockIdx.x * blockDim.x + threadIdx.x;   // float4 index, total 49152
    const float* src; bf16* dst; int off;
    if (i < 12288)      { src = wq; dst = g_wq; off = i; }
    else if (i < 16384) { src = wp; dst = g_wp; off = i - 12288; }
    else if (i < 32768) { src = w1; dst = g_w1; off = i - 16384; }
    else                { src = w2; dst = g_w2; off = i - 32768; }
    float4 v = *(const float4*)(src + off * 4);
    uint2 u = make_uint2(pack_bf2(v.x, v.y), pack_bf2(v.z, v.w));
    *(uint2*)(dst + off * 4) = u;
}

// ---------------------------------------------------------------------------
// bias gather: g_bias[h][n][m] = bias_table[rel_index[n][m]][h]
// ---------------------------------------------------------------------------
__global__ void bias_gather_kernel(const float* __restrict__ bias_table,
                                   const int* __restrict__ rel_index) {
    int m = threadIdx.x;
    int n = blockIdx.x;
    int h = blockIdx.y;
    int idx = rel_index[n * NTOK + m];
    g_bias[(h * NTOK + n) * NTOK + m] = bias_table[idx * NH + h];
}

// ---------------------------------------------------------------------------
// LayerNorm over C=128 (fp32 in, bf16 out): one warp per token.
// ---------------------------------------------------------------------------
template<bool PERMUTE>
__global__ __launch_bounds__(256)
void ln_kernel(const float* __restrict__ in,
               const float* __restrict__ gam,
               const float* __restrict__ bet,
               bf16* __restrict__ out) {
    int warp = threadIdx.x >> 5;
    int lane = threadIdx.x & 31;
    long t = (long)blockIdx.x * 8 + warp;
    const float4 v = *(const float4*)(in + t * CDIM + lane * 4);
    float s  = v.x + v.y + v.z + v.w;
    float sq = v.x * v.x + v.y * v.y + v.z * v.z + v.w * v.w;
    #pragma unroll
    for (int o = 16; o; o >>= 1) {
        s  += __shfl_xor_sync(0xffffffffu, s,  o);
        sq += __shfl_xor_sync(0xffffffffu, sq, o);
    }
    float mean = s * (1.0f / CDIM);
    float var  = sq * (1.0f / CDIM) - mean * mean;
    float rstd = rsqrtf(var + 1e-5f);
    const float4 g = *(const float4*)(gam + lane * 4);
    const float4 b = *(const float4*)(bet + lane * 4);
    uint2 u = make_uint2(pack_bf2((v.x - mean) * rstd * g.x + b.x,
                                  (v.y - mean) * rstd * g.y + b.y),
                         pack_bf2((v.z - mean) * rstd * g.z + b.z,
                                  (v.w - mean) * rstd * g.w + b.w));
    long orow = PERMUTE ? spatial_to_win(t) : t;
    *(uint2*)(out + orow * CDIM + lane * 4) = u;
}

// ---------------------------------------------------------------------------
// BF16 tensor-core GEMM v6: C[M,N] = A[M,K] @ W[N,K]^T (+ epilogue)
// Block 128x128, BK=32, FOUR-stage cp.async pipeline, prefetch distance 3,
// one sync per 32-k iter. 256 threads (8 warps: 2x4), warp tile 64x32,
// m16n8k16 + ldmatrix.x4.
// MODE 0: qkv  -> +bias; scale q-part (colBase==0); bf16 out [M,384]
// MODE 1: proj -> +bias; permute; += resid(x); fp32 g_x2  AND fused LN2 -> bf16 g_xw
// MODE 2: fc1  -> +bias; exact GELU; bf16 out [M,512]
// MODE 3: fc2  -> +bias; += resid(g_x2); fp32 out d_out
// ---------------------------------------------------------------------------
#define GS 40                  // smem row stride (halves): 32 + 8 pad
#define G_STAGE (256 * GS)     // As(128)+Ws(128) rows per stage
template<int MODE, int KT>
__global__ __launch_bounds__(256, 2)
void gemm_kernel(const bf16* __restrict__ A,
                 const bf16* __restrict__ Wt,
                 const float* __restrict__ bias,
                 const float* __restrict__ resid,
                 const float* __restrict__ gam,
                 const float* __restrict__ bet,
                 void* __restrict__ Cv,
                 int N) {
    extern __shared__ bf16 sm[];
    bf16* Asb[4] = { sm, sm + G_STAGE, sm + 2 * G_STAGE, sm + 3 * G_STAGE };
    bf16* Wsb[4] = { sm + 128 * GS, sm + G_STAGE + 128 * GS,
                     sm + 2 * G_STAGE + 128 * GS, sm + 3 * G_STAGE + 128 * GS };

    const int tid  = threadIdx.x;
    const int lane = tid & 31;
    const int warp = tid >> 5;
    const int warpM = warp >> 2;        // 0..1
    const int warpN = warp & 3;         // 0..3
    const int gid = lane >> 2;          // 0..7
    const int tig = lane & 3;           // 0..3

    const long rowBase = (long)blockIdx.y * 128;
    const int  colBase = blockIdx.x * 128;
    const int  K = KT;

    float cc[4][4][4];
    #pragma unroll
    for (int mi = 0; mi < 4; mi++)
        #pragma unroll
        for (int ni = 0; ni < 4; ni++)
            #pragma unroll
            for (int e = 0; e < 4; e++) cc[mi][ni][e] = 0.f;

    // loader: 2 threads per row, 2 x 16B chunks each (32 halves per row)
    const int ld_row = tid >> 1;               // 0..127
    const int ld_c0  = (tid & 1) * 16;         // half-offset 0 or 16

    auto load_tile = [&](int buf, int k0) {
        #pragma unroll
        for (int j = 0; j < 2; j++) {
            int c = ld_c0 + j * 8;
            cp_async16(&Asb[buf][ld_row * GS + c], A  + (rowBase + ld_row) * K + k0 + c);
        }
        #pragma unroll
        for (int j = 0; j < 2; j++) {
            int c = ld_c0 + j * 8;
            cp_async16(&Wsb[buf][ld_row * GS + c], Wt + (long)(colBase + ld_row) * K + k0 + c);
        }
    };

    constexpr int nk = KT / 32;   // >= 4 always
    load_tile(0, 0);   cp_commit();
    load_tile(1, 32);  cp_commit();
    load_tile(2, 64);  cp_commit();

    // ldmatrix lane-address components
    const int a_r = (lane & 7) + ((lane >> 3) & 1) * 8;
    const int a_k = (lane >> 4) * 8;
    const int b_n = (lane & 7) + (lane >> 4) * 8;
    const int b_k = ((lane >> 3) & 1) * 8;

    #pragma unroll
    for (int it = 0; it < nk; it++) {
        // wait for stage it: allow outstanding = min(2, nk-1-it) groups
        const int rem = nk - 1 - it;
        if (rem >= 2) cp_wait<2>();
        else if (rem == 1) cp_wait<1>();
        else cp_wait<0>();
        __syncthreads();
        // prefetch stage it+3 (stage (it+3)&3 == (it-1)&3, consumed at it-1)
        if (it + 3 < nk) { load_tile((it + 3) & 3, (it + 3) * 32); cp_commit(); }

        const bf16* As = Asb[it & 3];
        const bf16* Ws = Wsb[it & 3];
        #pragma unroll
        for (int ks = 0; ks < 2; ks++) {
            const int kk = ks * 16;
            uint32_t af[4][4];
            uint32_t bf[4][2];
            #pragma unroll
            for (int mi = 0; mi < 4; mi++)
                ldsm_x4(af[mi], As + (warpM * 64 + mi * 16 + a_r) * GS + kk + a_k);
            #pragma unroll
            for (int np = 0; np < 2; np++) {
                uint32_t r4[4];
                ldsm_x4(r4, Ws + (warpN * 32 + np * 16 + b_n) * GS + kk + b_k);
                bf[2 * np][0] = r4[0]; bf[2 * np][1] = r4[1];
                bf[2 * np + 1][0] = r4[2]; bf[2 * np + 1][1] = r4[3];
            }
            #pragma unroll
            for (int mi = 0; mi < 4; mi++)
                #pragma unroll
                for (int ni = 0; ni < 4; ni++)
                    mma_bf16(cc[mi][ni], af[mi], bf[ni]);
        }
    }

    if (MODE == 1) {
        // fused: x2 = resid + proj_out (+bias), write fp32 g_x2;
        // then LayerNorm(x2) over full 128-col rows -> bf16 g_xw.
        __syncthreads();                 // all warps done with smem stages
        float* red = (float*)sm;         // [128][2] row sums
        if (tid < 128) { red[2 * tid] = 0.f; red[2 * tid + 1] = 0.f; }
        __syncthreads();

        long orows[4][2];
        float* C = (float*)Cv;
        #pragma unroll
        for (int mi = 0; mi < 4; mi++) {
            #pragma unroll
            for (int half = 0; half < 2; half++) {
                int rloc = warpM * 64 + mi * 16 + gid + half * 8;
                long orow = win_to_spatial(rowBase + rloc);
                orows[mi][half] = orow;
                float s = 0.f, sq = 0.f;
                #pragma unroll
                for (int ni = 0; ni < 4; ni++) {
                    int col = warpN * 32 + ni * 8 + 2 * tig;
                    const float2 r = *(const float2*)(resid + orow * CDIM + col);
                    float v0 = cc[mi][ni][half * 2 + 0] + bias[col]     + r.x;
                    float v1 = cc[mi][ni][half * 2 + 1] + bias[col + 1] + r.y;
                    cc[mi][ni][half * 2 + 0] = v0;
                    cc[mi][ni][half * 2 + 1] = v1;
                    *(float2*)(C + orow * CDIM + col) = make_float2(v0, v1);
                    s += v0 + v1; sq += v0 * v0 + v1 * v1;
                }
                s  += __shfl_xor_sync(0xffffffffu, s, 1);
                sq += __shfl_xor_sync(0xffffffffu, sq, 1);
                s  += __shfl_xor_sync(0xffffffffu, s, 2);
                sq += __shfl_xor_sync(0xffffffffu, sq, 2);
                if (tig == 0) {
                    atomicAdd(&red[2 * rloc],     s);
                    atomicAdd(&red[2 * rloc + 1], sq);
                }
            }
        }
        __syncthreads();
        #pragma unroll
        for (int mi = 0; mi < 4; mi++) {
            #pragma unroll
            for (int half = 0; half < 2; half++) {
                int rloc = warpM * 64 + mi * 16 + gid + half * 8;
                long orow = orows[mi][half];
                float mean = red[2 * rloc] * (1.0f / CDIM);
                float var  = red[2 * rloc + 1] * (1.0f / CDIM) - mean * mean;
                float rstd = rsqrtf(var + 1e-5f);
                #pragma unroll
                for (int ni = 0; ni < 4; ni++) {
                    int col = warpN * 32 + ni * 8 + 2 * tig;
                    float v0 = cc[mi][ni][half * 2 + 0];
                    float v1 = cc[mi][ni][half * 2 + 1];
                    float y0 = (v0 - mean) * rstd * gam[col]     + bet[col];
                    float y1 = (v1 - mean) * rstd * gam[col + 1] + bet[col + 1];
                    *(uint32_t*)(g_xw + orow * CDIM + col) = pack_bf2(y0, y1);
                }
            }
        }
        return;
    }

    // epilogue (MODE 0/2/3)
    #pragma unroll
    for (int mi = 0; mi < 4; mi++) {
        #pragma unroll
        for (int half = 0; half < 2; half++) {
            long row = rowBase + warpM * 64 + mi * 16 + gid + half * 8;
            #pragma unroll
            for (int ni = 0; ni < 4; ni++) {
                int col = colBase + warpN * 32 + ni * 8 + 2 * tig;
                float v0 = cc[mi][ni][half * 2 + 0] + bias[col];
                float v1 = cc[mi][ni][half * 2 + 1] + bias[col + 1];
                if (MODE == 0) {
                    if (colBase == 0) { v0 *= 0.17677669529663687f; v1 *= 0.17677669529663687f; }
                }
                if (MODE == 2) {
                    v0 = 0.5f * v0 * (1.0f + erff(v0 * 0.70710678118654752f));
                    v1 = 0.5f * v1 * (1.0f + erff(v1 * 0.70710678118654752f));
                }
                if (MODE == 3) {
                    float* C = (float*)Cv;
                    const float2 r = *(const float2*)(resid + row * CDIM + col);
                    *(float2*)(C + row * CDIM + col) = make_float2(v0 + r.x, v1 + r.y);
                } else {
                    bf16* C = (bf16*)Cv;
                    *(uint32_t*)(C + row * (long)N + col) = pack_bf2(v0, v1);
                }
            }
        }
    }
}

// ---------------------------------------------------------------------------
// BF16 tensor-core window attention.
// smem ALIASED: ps[128][120] overlaps dead qs/ks after S phase (R3 pattern).
// Layout (bf16 elems): qs@0 [128][40], ks@5120 [112][40]  (both < 15360)
//                      ps@0 [128][120] (aliases qs+ks), vsr@15360 [112][40]
// __launch_bounds__(128,4): 4 CTAs/SM (smem 38.75KB each).
// ---------------------------------------------------------------------------
#define AQS 40
#define PSS 120
#define NPAD 112
#define ATTN_ELEMS (128 * PSS + NPAD * AQS)   // 19840 bf16 = 39680 B
__global__ __launch_bounds__(128, 4)
void attn_kernel() {
    extern __shared__ bf16 asm_[];
    bf16* qs  = asm_;                          // [128][40]   (aliased by ps later)
    bf16* ks  = asm_ + 128 * AQS;              // [112][40]   (aliased by ps later)
    bf16* ps  = asm_;                          // [128][120]
    bf16* vsr = asm_ + 128 * PSS;              // [112][40]

    const int w = blockIdx.x;
    const int h = blockIdx.y;
    const int tid  = threadIdx.x;
    const int warp = tid >> 5;
    const int lane = tid & 31;
    const int gid = lane >> 2;
    const int tig = lane & 3;

    const bf16* base = g_qkv + (size_t)w * NTOK * QKVN + h * HD;

    for (int i = tid; i < NTOK * 4; i += 128) {
        int m = i >> 2, c = (i & 3) * 8;
        *(uint4*)&qs [m * AQS + c] = *(const uint4*)(base + m * QKVN + c);
        *(uint4*)&ks [m * AQS + c] = *(const uint4*)(base + m * QKVN + CDIM + c);
        *(uint4*)&vsr[m * AQS + c] = *(const uint4*)(base + m * QKVN + 2 * CDIM + c);
    }
    const uint4 z4 = make_uint4(0, 0, 0, 0);
    for (int i = tid; i < 30 * 4; i += 128) {
        int m = 98 + (i >> 2), c = (i & 3) * 8;
        *(uint4*)&qs[m * AQS + c] = z4;
        if (m < NPAD) {
            *(uint4*)&ks [m * AQS + c] = z4;
            *(uint4*)&vsr[m * AQS + c] = z4;
        }
    }
    __syncthreads();

    const int a_r = (lane & 7) + ((lane >> 3) & 1) * 8;
    const int a_k = (lane >> 4) * 8;
    const int b_n = (lane & 7) + (lane >> 4) * 8;
    const int b_k = ((lane >> 3) & 1) * 8;
    const int t_r = (lane & 7) + ((lane >> 3) & 1) * 8;
    const int t_c = (lane >> 4) * 8;

    float cc[2][14][4];
    #pragma unroll
    for (int mi = 0; mi < 2; mi++)
        #pragma unroll
        for (int ni = 0; ni < 14; ni++)
            #pragma unroll
            for (int e = 0; e < 4; e++) cc[mi][ni][e] = 0.f;

    #pragma unroll
    for (int ksx = 0; ksx < 2; ksx++) {
        const int kk = ksx * 16;
        uint32_t af[2][4];
        #pragma unroll
        for (int mi = 0; mi < 2; mi++)
            ldsm_x4(af[mi], qs + (warp * 32 + mi * 16 + a_r) * AQS + kk + a_k);
        #pragma unroll
        for (int np = 0; np < 7; np++) {
            uint32_t r4[4];
            ldsm_x4(r4, ks + (np * 16 + b_n) * AQS + kk + b_k);
            uint32_t b0[2] = { r4[0], r4[1] };
            uint32_t b1[2] = { r4[2], r4[3] };
            mma_bf16(cc[0][2 * np],     af[0], b0);
            mma_bf16(cc[1][2 * np],     af[1], b0);
            mma_bf16(cc[0][2 * np + 1], af[0], b1);
            mma_bf16(cc[1][2 * np + 1], af[1], b1);
        }
    }

    float rsum[2][2] = {{0.f, 0.f}, {0.f, 0.f}};
    const float* gb = g_bias + h * NTOK * NTOK;
    #pragma unroll
    for (int mi = 0; mi < 2; mi++) {
        int r0 = warp * 32 + mi * 16 + gid;
        int r1 = r0 + 8;
        const float* b0p = gb + (r0 < NTOK ? r0 : NTOK - 1) * NTOK;
        const float* b1p = gb + (r1 < NTOK ? r1 : NTOK - 1) * NTOK;
        #pragma unroll
        for (int ni = 0; ni < 14; ni++) {
            int c0 = ni * 8 + 2 * tig;
            int c1 = c0 + 1;
            int cc0 = c0 < NTOK ? c0 : NTOK - 1;
            int cc1 = c1 < NTOK ? c1 : NTOK - 1;
            float e;
            e = (c0 < NTOK) ? __expf(cc[mi][ni][0] + b0p[cc0]) : 0.f; cc[mi][ni][0] = e; rsum[mi][0] += e;
            e = (c1 < NTOK) ? __expf(cc[mi][ni][1] + b0p[cc1]) : 0.f; cc[mi][ni][1] = e; rsum[mi][0] += e;
            e = (c0 < NTOK) ? __expf(cc[mi][ni][2] + b1p[cc0]) : 0.f; cc[mi][ni][2] = e; rsum[mi][1] += e;
            e = (c1 < NTOK) ? __expf(cc[mi][ni][3] + b1p[cc1]) : 0.f; cc[mi][ni][3] = e; rsum[mi][1] += e;
        }
    }
    float inv[2][2];
    #pragma unroll
    for (int mi = 0; mi < 2; mi++)
        #pragma unroll
        for (int hf = 0; hf < 2; hf++) {
            float s = rsum[mi][hf];
            s += __shfl_xor_sync(0xffffffffu, s, 1);
            s += __shfl_xor_sync(0xffffffffu, s, 2);
            inv[mi][hf] = 1.0f / s;
        }

    __syncthreads();   // all warps done reading qs/ks before ps overwrites them

    // write normalized P as bf16 (own rows only -> warp-local sync after)
    #pragma unroll
    for (int mi = 0; mi < 2; mi++) {
        int r0 = warp * 32 + mi * 16 + gid;
        #pragma unroll
        for (int ni = 0; ni < 14; ni++) {
            int col = ni * 8 + 2 * tig;
            *(uint32_t*)&ps[r0 * PSS + col] =
                pack_bf2(cc[mi][ni][0] * inv[mi][0], cc[mi][ni][1] * inv[mi][0]);
            *(uint32_t*)&ps[(r0 + 8) * PSS + col] =
                pack_bf2(cc[mi][ni][2] * inv[mi][1], cc[mi][ni][3] * inv[mi][1]);
        }
    }
    __syncwarp();

    float oo[2][4][4];
    #pragma unroll
    for (int mi = 0; mi < 2; mi++)
        #pragma unroll
        for (int ni = 0; ni < 4; ni++)
            #pragma unroll
            for (int e = 0; e < 4; e++) oo[mi][ni][e] = 0.f;

    #pragma unroll
    for (int k2 = 0; k2 < 7; k2++) {
        const int kk = k2 * 16;
        uint32_t af[2][4];
        #pragma unroll
        for (int mi = 0; mi < 2; mi++)
            ldsm_x4(af[mi], ps + (warp * 32 + mi * 16 + a_r) * PSS + kk + a_k);
        #pragma unroll
        for (int np = 0; np < 2; np++) {
            int n0 = np * 16;
            uint32_t r4[4];
            ldsm_x4_t(r4, vsr + (kk + t_r) * AQS + n0 + t_c);
            uint32_t b0[2] = { r4[0], r4[1] };
            uint32_t b1[2] = { r4[2], r4[3] };
            mma_bf16(oo[0][2 * np],     af[0], b0);
            mma_bf16(oo[1][2 * np],     af[1], b0);
            mma_bf16(oo[0][2 * np + 1], af[0], b1);
            mma_bf16(oo[1][2 * np + 1], af[1], b1);
        }
    }

    #pragma unroll
    for (int mi = 0; mi < 2; mi++) {
        #pragma unroll
        for (int hf = 0; hf < 2; hf++) {
            int row = warp * 32 + mi * 16 + gid + hf * 8;
            if (row < NTOK) {
                bf16* op = g_attn + ((size_t)w * NTOK + row) * CDIM + h * HD;
                #pragma unroll
                for (int ni = 0; ni < 4; ni++) {
                    int col = ni * 8 + 2 * tig;
                    *(uint32_t*)(op + col) =
                        pack_bf2(oo[mi][ni][hf * 2], oo[mi][ni][hf * 2 + 1]);
                }
            }
        }
    }
}

// ---------------------------------------------------------------------------
// launcher
// ---------------------------------------------------------------------------
extern "C" void kernel_launch(void* const* d_in, const int* in_sizes, int n_in,
                              void* d_out, int out_size) {
    const float* x          = (const float*)d_in[0];
    const float* norm1_w    = (const float*)d_in[1];
    const float* norm1_b    = (const float*)d_in[2];
    const float* qkv_w      = (const float*)d_in[3];
    const float* qkv_b      = (const float*)d_in[4];
    const float* bias_table = (const float*)d_in[5];
    const float* proj_w     = (const float*)d_in[6];
    const float* proj_b     = (const float*)d_in[7];
    const float* norm2_w    = (const float*)d_in[8];
    const float* norm2_b    = (const float*)d_in[9];
    const float* fc1_w      = (const float*)d_in[10];
    const float* fc1_b      = (const float*)d_in[11];
    const float* fc2_w      = (const float*)d_in[12];
    const float* fc2_b      = (const float*)d_in[13];
    const int*   rel_index  = (const int*)d_in[14];
    float* out = (float*)d_out;

    bf16 *p_xw, *p_qkv, *p_attn, *p_h;
    bf16 *p_wq, *p_wp, *p_w1, *p_w2;
    float *p_x2;
    cudaGetSymbolAddress((void**)&p_xw,   g_xw);
    cudaGetSymbolAddress((void**)&p_qkv,  g_qkv);
    cudaGetSymbolAddress((void**)&p_attn, g_attn);
    cudaGetSymbolAddress((void**)&p_x2,   g_x2);
    cudaGetSymbolAddress((void**)&p_h,    g_h);
    cudaGetSymbolAddress((void**)&p_wq,   g_wq);
    cudaGetSymbolAddress((void**)&p_wp,   g_wp);
    cudaGetSymbolAddress((void**)&p_w1,   g_w1);
    cudaGetSymbolAddress((void**)&p_w2,   g_w2);

    const int GEMM_SMEM = 4 * G_STAGE * (int)sizeof(bf16);   // 81920
    const int ATTN_SMEM = ATTN_ELEMS * (int)sizeof(bf16);    // 39680
    cudaFuncSetAttribute((const void*)gemm_kernel<0,128>, cudaFuncAttributeMaxDynamicSharedMemorySize, GEMM_SMEM);
    cudaFuncSetAttribute((const void*)gemm_kernel<1,128>, cudaFuncAttributeMaxDynamicSharedMemorySize, GEMM_SMEM);
    cudaFuncSetAttribute((const void*)gemm_kernel<2,128>, cudaFuncAttributeMaxDynamicSharedMemorySize, GEMM_SMEM);
    cudaFuncSetAttribute((const void*)gemm_kernel<3,512>, cudaFuncAttributeMaxDynamicSharedMemorySize, GEMM_SMEM);
    cudaFuncSetAttribute((const void*)attn_kernel,        cudaFuncAttributeMaxDynamicSharedMemorySize, ATTN_SMEM);

    // 0) weight conversion + bias gather
    cvt_weights_kernel<<<49152 / 256, 256>>>(qkv_w, proj_w, fc1_w, fc2_w);
    bias_gather_kernel<<<dim3(NTOK, NH), NTOK>>>(bias_table, rel_index);

    // 1) LN1 + window partition (fp32 -> bf16)
    ln_kernel<true><<<TOK / 8, 256>>>(x, norm1_w, norm1_b, p_xw);

    // 2) QKV gemm (+ q scale), bf16 out
    gemm_kernel<0,128><<<dim3(QKVN / 128, TOK / 128), 256, GEMM_SMEM>>>(
        p_xw, p_wq, qkv_b, nullptr, nullptr, nullptr, p_qkv, QKVN);

    // 3) window attention (bf16 tensor cores)
    attn_kernel<<<dim3(NWIN, NH), 128, ATTN_SMEM>>>();

    // 4) proj gemm + window reverse + residual(x) -> g_x2 (fp32)  + fused LN2 -> g_xw (bf16)
    gemm_kernel<1,128><<<dim3(CDIM / 128, TOK / 128), 256, GEMM_SMEM>>>(
        p_attn, p_wp, proj_b, x, norm2_w, norm2_b, p_x2, CDIM);

    // 5) fc1 + exact GELU, bf16 out
    gemm_kernel<2,128><<<dim3(CH / 128, TOK / 128), 256, GEMM_SMEM>>>(
        p_xw, p_w1, fc1_b, nullptr, nullptr, nullptr, p_h, CH);

    // 6) fc2 + residual(g_x2) -> d_out (fp32)
    gemm_kernel<3,512><<<dim3(CDIM / 128, TOK / 128), 256, GEMM_SMEM>>>(
        p_h, p_w2, fc2_b, p_x2, nullptr, nullptr, out, CDIM);

    (void)in_sizes; (void)n_in; (void)out_size;
}

// round 10
// speedup vs baseline: 1.8125x; 1.0194x over previous
#include <cuda_runtime.h>
#include <cuda_bf16.h>
#include <math.h>
#include <stdint.h>

// ---------------------------------------------------------------------------
// Problem constants
// ---------------------------------------------------------------------------
#define TOK   50176      // 2*8*56*56
#define CDIM  128
#define CH    512
#define NWIN  512        // 2 * 4*8*8
#define NTOK  98         // 2*7*7
#define NH    4
#define HD    32
#define QKVN  384

typedef __nv_bfloat16  bf16;
typedef __nv_bfloat162 bf162;

// ---------------------------------------------------------------------------
// Scratch (device globals: allocation-free, graph-capture safe)
// ---------------------------------------------------------------------------
__device__ bf16  g_xw  [(size_t)TOK * CDIM];   // LN1 out (window order) / LN2 out (spatial)
__device__ bf16  g_qkv [(size_t)TOK * QKVN];   // qkv, window order
__device__ bf16  g_attn[(size_t)TOK * CDIM];   // attention out, window order
__device__ float g_x2  [(size_t)TOK * CDIM];   // x + proj (spatial, fp32)
__device__ bf16  g_h   [(size_t)TOK * CH];     // fc1 output
__device__ float g_bias[NH * NTOK * NTOK];     // gathered attention bias (fp32)
// bf16 weights
__device__ bf16  g_wq[QKVN * CDIM];
__device__ bf16  g_wp[CDIM * CDIM];
__device__ bf16  g_w1[CH * CDIM];
__device__ bf16  g_w2[CDIM * CH];

// ---------------------------------------------------------------------------
// index helpers
// ---------------------------------------------------------------------------
__device__ __forceinline__ long win_to_spatial(long row) {
    int w = (int)(row / NTOK);
    int n = (int)(row % NTOK);
    int b   = w >> 8;
    int rem = w & 255;
    int wdi = rem >> 6, whi = (rem >> 3) & 7, wwi = rem & 7;
    int zd = n / 49; int r2 = n % 49; int zh = r2 / 7, zw = r2 % 7;
    int d  = wdi * 2 + zd;
    int hh = whi * 7 + zh;
    int xx = wwi * 7 + zw;
    return (((long)(b * 8 + d) * 56) + hh) * 56 + xx;
}

__device__ __forceinline__ long spatial_to_win(long t) {
    int b  = (int)(t / 25088);
    int r  = (int)(t % 25088);
    int d  = r / 3136; r %= 3136;
    int hh = r / 56;
    int xx = r % 56;
    int widx = ((b * 4 + (d >> 1)) * 8 + hh / 7) * 8 + xx / 7;
    int n    = ((d & 1) * 7 + hh % 7) * 7 + xx % 7;
    return (long)widx * NTOK + n;
}

// ---------------------------------------------------------------------------
// async copy + ldmatrix + mma helpers
// ---------------------------------------------------------------------------
__device__ __forceinline__ void cp_async16(bf16* smem_dst, const bf16* gmem_src) {
    uint32_t s = (uint32_t)__cvta_generic_to_shared(smem_dst);
    asm volatile("cp.async.cg.shared.global [%0], [%1], 16;\n" :: "r"(s), "l"(gmem_src));
}
__device__ __forceinline__ void cp_commit() { asm volatile("cp.async.commit_group;\n"); }
template<int N>
__device__ __forceinline__ void cp_wait() { asm volatile("cp.async.wait_group %0;\n" :: "n"(N)); }

__device__ __forceinline__ void ldsm_x4(uint32_t r[4], const bf16* p) {
    uint32_t a = (uint32_t)__cvta_generic_to_shared(p);
    asm volatile("ldmatrix.sync.aligned.m8n8.x4.shared.b16 {%0,%1,%2,%3}, [%4];\n"
                 : "=r"(r[0]), "=r"(r[1]), "=r"(r[2]), "=r"(r[3]) : "r"(a));
}
__device__ __forceinline__ void ldsm_x4_t(uint32_t r[4], const bf16* p) {
    uint32_t a = (uint32_t)__cvta_generic_to_shared(p);
    asm volatile("ldmatrix.sync.aligned.m8n8.x4.trans.shared.b16 {%0,%1,%2,%3}, [%4];\n"
                 : "=r"(r[0]), "=r"(r[1]), "=r"(r[2]), "=r"(r[3]) : "r"(a));
}
__device__ __forceinline__ void mma_bf16(float c[4], const uint32_t a[4], const uint32_t b[2]) {
    asm volatile(
        "mma.sync.aligned.m16n8k16.row.col.f32.bf16.bf16.f32 "
        "{%0,%1,%2,%3}, {%4,%5,%6,%7}, {%8,%9}, {%0,%1,%2,%3};\n"
        : "+f"(c[0]), "+f"(c[1]), "+f"(c[2]), "+f"(c[3])
        : "r"(a[0]), "r"(a[1]), "r"(a[2]), "r"(a[3]), "r"(b[0]), "r"(b[1]));
}

__device__ __forceinline__ uint32_t pack_bf2(float a, float b) {
    bf162 p = __float22bfloat162_rn(make_float2(a, b));
    return *(uint32_t*)&p;
}

// ---------------------------------------------------------------------------
// fused weight conversion fp32 -> bf16 (float4 granularity)
// ---------------------------------------------------------------------------
__global__ void cvt_weights_kernel(const float* __restrict__ wq,
                                   const float* __restrict__ wp,
                                   const float* __restrict__ w1,
                                   const float* __restrict__ w2) {
    int i = blockIdx.x * blockDim.x + threadIdx.x;   // float4 index, total 49152
    const float* src; bf16* dst; int off;
    if (i < 12288)      { src = wq; dst = g_wq; off = i; }
    else if (i < 16384) { src = wp; dst = g_wp; off = i - 12288; }
    else if (i < 32768) { src = w1; dst = g_w1; off = i - 16384; }
    else                { src = w2; dst = g_w2; off = i - 32768; }
    float4 v = *(const float4*)(src + off * 4);
    uint2 u = make_uint2(pack_bf2(v.x, v.y), pack_bf2(v.z, v.w));
    *(uint2*)(dst + off * 4) = u;
}

// ---------------------------------------------------------------------------
// bias gather: g_bias[h][n][m] = bias_table[rel_index[n][m]][h]
// ---------------------------------------------------------------------------
__global__ void bias_gather_kernel(const float* __restrict__ bias_table,
                                   const int* __restrict__ rel_index) {
    int m = threadIdx.x;
    int n = blockIdx.x;
    int h = blockIdx.y;
    int idx = rel_index[n * NTOK + m];
    g_bias[(h * NTOK + n) * NTOK + m] = bias_table[idx * NH + h];
}

// ---------------------------------------------------------------------------
// LayerNorm over C=128 (fp32 in, bf16 out): one warp per token.
// ---------------------------------------------------------------------------
template<bool PERMUTE>
__global__ __launch_bounds__(256)
void ln_kernel(const float* __restrict__ in,
               const float* __restrict__ gam,
               const float* __restrict__ bet,
               bf16* __restrict__ out) {
    int warp = threadIdx.x >> 5;
    int lane = threadIdx.x & 31;
    long t = (long)blockIdx.x * 8 + warp;
    const float4 v = *(const float4*)(in + t * CDIM + lane * 4);
    float s  = v.x + v.y + v.z + v.w;
    float sq = v.x * v.x + v.y * v.y + v.z * v.z + v.w * v.w;
    #pragma unroll
    for (int o = 16; o; o >>= 1) {
        s  += __shfl_xor_sync(0xffffffffu, s,  o);
        sq += __shfl_xor_sync(0xffffffffu, sq, o);
    }
    float mean = s * (1.0f / CDIM);
    float var  = sq * (1.0f / CDIM) - mean * mean;
    float rstd = rsqrtf(var + 1e-5f);
    const float4 g = *(const float4*)(gam + lane * 4);
    const float4 b = *(const float4*)(bet + lane * 4);
    uint2 u = make_uint2(pack_bf2((v.x - mean) * rstd * g.x + b.x,
                                  (v.y - mean) * rstd * g.y + b.y),
                         pack_bf2((v.z - mean) * rstd * g.z + b.z,
                                  (v.w - mean) * rstd * g.w + b.w));
    long orow = PERMUTE ? spatial_to_win(t) : t;
    *(uint2*)(out + orow * CDIM + lane * 4) = u;
}

// ---------------------------------------------------------------------------
// BF16 GEMM (R5 exact): 128x128 block, BK=32, 3-stage cp.async, warp 64x32.
// MODE 0: qkv  -> +bias; scale q-part (colBase==0); bf16 out [M,384]
// MODE 2: fc1  -> +bias; exact GELU; bf16 out [M,512]
// ---------------------------------------------------------------------------
#define GS 40                  // smem row stride (halves): 32 + 8 pad
#define G_STAGE (256 * GS)     // As(128)+Ws(128) rows per stage
template<int MODE, int KT>
__global__ __launch_bounds__(256, 2)
void gemm_kernel(const bf16* __restrict__ A,
                 const bf16* __restrict__ Wt,
                 const float* __restrict__ bias,
                 void* __restrict__ Cv,
                 int N) {
    extern __shared__ bf16 sm[];
    bf16* Asb[3] = { sm, sm + G_STAGE, sm + 2 * G_STAGE };
    bf16* Wsb[3] = { sm + 128 * GS, sm + G_STAGE + 128 * GS, sm + 2 * G_STAGE + 128 * GS };

    const int tid  = threadIdx.x;
    const int lane = tid & 31;
    const int warp = tid >> 5;
    const int warpM = warp >> 2;        // 0..1
    const int warpN = warp & 3;         // 0..3
    const int gid = lane >> 2;          // 0..7
    const int tig = lane & 3;           // 0..3

    const long rowBase = (long)blockIdx.y * 128;
    const int  colBase = blockIdx.x * 128;
    const int  K = KT;

    float cc[4][4][4];
    #pragma unroll
    for (int mi = 0; mi < 4; mi++)
        #pragma unroll
        for (int ni = 0; ni < 4; ni++)
            #pragma unroll
            for (int e = 0; e < 4; e++) cc[mi][ni][e] = 0.f;

    const int ld_row = tid >> 2;        // 0..63
    const int ld_kq  = (tid & 3) * 8;   // halves

    auto load_tile = [&](int buf, int k0) {
        #pragma unroll
        for (int r = 0; r < 2; r++) {
            int m = ld_row + r * 64;
            cp_async16(&Asb[buf][m * GS + ld_kq], A + (rowBase + m) * K + k0 + ld_kq);
        }
        #pragma unroll
        for (int r = 0; r < 2; r++) {
            int n = ld_row + r * 64;
            cp_async16(&Wsb[buf][n * GS + ld_kq], Wt + (long)(colBase + n) * K + k0 + ld_kq);
        }
    };

    constexpr int nk = KT / 32;
    load_tile(0, 0);  cp_commit();
    load_tile(1, 32); cp_commit();

    const int a_r = (lane & 7) + ((lane >> 3) & 1) * 8;
    const int a_k = (lane >> 4) * 8;
    const int b_n = (lane & 7) + (lane >> 4) * 8;
    const int b_k = ((lane >> 3) & 1) * 8;

    #pragma unroll
    for (int it = 0; it < nk; it++) {
        cp_wait<1>();
        __syncthreads();
        if (it + 2 < nk) load_tile((it + 2) % 3, (it + 2) * 32);
        cp_commit();

        const bf16* As = Asb[it % 3];
        const bf16* Ws = Wsb[it % 3];
        #pragma unroll
        for (int ks = 0; ks < 2; ks++) {
            const int kk = ks * 16;
            uint32_t af[4][4];
            uint32_t bf[4][2];
            #pragma unroll
            for (int mi = 0; mi < 4; mi++)
                ldsm_x4(af[mi], As + (warpM * 64 + mi * 16 + a_r) * GS + kk + a_k);
            #pragma unroll
            for (int np = 0; np < 2; np++) {
                uint32_t r4[4];
                ldsm_x4(r4, Ws + (warpN * 32 + np * 16 + b_n) * GS + kk + b_k);
                bf[2 * np][0] = r4[0]; bf[2 * np][1] = r4[1];
                bf[2 * np + 1][0] = r4[2]; bf[2 * np + 1][1] = r4[3];
            }
            #pragma unroll
            for (int mi = 0; mi < 4; mi++)
                #pragma unroll
                for (int ni = 0; ni < 4; ni++)
                    mma_bf16(cc[mi][ni], af[mi], bf[ni]);
        }
    }

    // epilogue (MODE 0/2)
    #pragma unroll
    for (int mi = 0; mi < 4; mi++) {
        #pragma unroll
        for (int half = 0; half < 2; half++) {
            long row = rowBase + warpM * 64 + mi * 16 + gid + half * 8;
            #pragma unroll
            for (int ni = 0; ni < 4; ni++) {
                int col = colBase + warpN * 32 + ni * 8 + 2 * tig;
                float v0 = cc[mi][ni][half * 2 + 0] + bias[col];
                float v1 = cc[mi][ni][half * 2 + 1] + bias[col + 1];
                if (MODE == 0) {
                    if (colBase == 0) { v0 *= 0.17677669529663687f; v1 *= 0.17677669529663687f; }
                }
                if (MODE == 2) {
                    v0 = 0.5f * v0 * (1.0f + erff(v0 * 0.70710678118654752f));
                    v1 = 0.5f * v1 * (1.0f + erff(v1 * 0.70710678118654752f));
                }
                bf16* C = (bf16*)Cv;
                *(uint32_t*)(C + row * (long)N + col) = pack_bf2(v0, v1);
            }
        }
    }
}

// ---------------------------------------------------------------------------
// BF16 GEMM-64: 64x128 block, BK=32, 3-stage, 256 threads (8 warps 2x4),
// warp tile 32x32, __launch_bounds__(256,3) -> 3 CTAs/SM, grid 784 CTAs.
// For the N=128 wave-starved launches:
// MODE 1: proj -> +bias; permute; += resid(x); fp32 g_x2  AND fused LN2 -> bf16 g_xw
// MODE 3: fc2  -> +bias; += resid(g_x2); fp32 out d_out
// ---------------------------------------------------------------------------
#define G64_STAGE (192 * GS)   // As(64)+Ws(128) rows per stage
template<int MODE, int KT>
__global__ __launch_bounds__(256, 3)
void gemm64_kernel(const bf16* __restrict__ A,
                   const bf16* __restrict__ Wt,
                   const float* __restrict__ bias,
                   const float* __restrict__ resid,
                   const float* __restrict__ gam,
                   const float* __restrict__ bet,
                   float* __restrict__ C) {
    extern __shared__ bf16 sm[];
    bf16* Asb[3] = { sm, sm + G64_STAGE, sm + 2 * G64_STAGE };
    bf16* Wsb[3] = { sm + 64 * GS, sm + G64_STAGE + 64 * GS, sm + 2 * G64_STAGE + 64 * GS };

    const int tid  = threadIdx.x;
    const int lane = tid & 31;
    const int warp = tid >> 5;
    const int warpM = warp >> 2;        // 0..1  -> 32-row slice
    const int warpN = warp & 3;         // 0..3  -> 32-col slice
    const int gid = lane >> 2;          // 0..7
    const int tig = lane & 3;           // 0..3

    const long rowBase = (long)blockIdx.x * 64;
    const int  K = KT;

    float cc[2][4][4];
    #pragma unroll
    for (int mi = 0; mi < 2; mi++)
        #pragma unroll
        for (int ni = 0; ni < 4; ni++)
            #pragma unroll
            for (int e = 0; e < 4; e++) cc[mi][ni][e] = 0.f;

    const int ld_rowA = tid >> 2;       // 0..63
    const int ld_kq   = (tid & 3) * 8;

    auto load_tile = [&](int buf, int k0) {
        cp_async16(&Asb[buf][ld_rowA * GS + ld_kq], A + (rowBase + ld_rowA) * K + k0 + ld_kq);
        #pragma unroll
        for (int r = 0; r < 2; r++) {
            int n = ld_rowA + r * 64;
            cp_async16(&Wsb[buf][n * GS + ld_kq], Wt + (long)n * K + k0 + ld_kq);
        }
    };

    constexpr int nk = KT / 32;
    load_tile(0, 0);  cp_commit();
    load_tile(1, 32); cp_commit();

    const int a_r = (lane & 7) + ((lane >> 3) & 1) * 8;
    const int a_k = (lane >> 4) * 8;
    const int b_n = (lane & 7) + (lane >> 4) * 8;
    const int b_k = ((lane >> 3) & 1) * 8;

    #pragma unroll
    for (int it = 0; it < nk; it++) {
        cp_wait<1>();
        __syncthreads();
        if (it + 2 < nk) load_tile((it + 2) % 3, (it + 2) * 32);
        cp_commit();

        const bf16* As = Asb[it % 3];
        const bf16* Ws = Wsb[it % 3];
        #pragma unroll
        for (int ks = 0; ks < 2; ks++) {
            const int kk = ks * 16;
            uint32_t af[2][4];
            uint32_t bf[4][2];
            #pragma unroll
            for (int mi = 0; mi < 2; mi++)
                ldsm_x4(af[mi], As + (warpM * 32 + mi * 16 + a_r) * GS + kk + a_k);
            #pragma unroll
            for (int np = 0; np < 2; np++) {
                uint32_t r4[4];
                ldsm_x4(r4, Ws + (warpN * 32 + np * 16 + b_n) * GS + kk + b_k);
                bf[2 * np][0] = r4[0]; bf[2 * np][1] = r4[1];
                bf[2 * np + 1][0] = r4[2]; bf[2 * np + 1][1] = r4[3];
            }
            #pragma unroll
            for (int mi = 0; mi < 2; mi++)
                #pragma unroll
                for (int ni = 0; ni < 4; ni++)
                    mma_bf16(cc[mi][ni], af[mi], bf[ni]);
        }
    }

    if (MODE == 1) {
        __syncthreads();                 // done with smem stages
        float* red = (float*)sm;         // [64][2] row sums
        if (tid < 64) { red[2 * tid] = 0.f; red[2 * tid + 1] = 0.f; }
        __syncthreads();

        long orows[2][2];
        #pragma unroll
        for (int mi = 0; mi < 2; mi++) {
            #pragma unroll
            for (int half = 0; half < 2; half++) {
                int rloc = warpM * 32 + mi * 16 + gid + half * 8;
                long orow = win_to_spatial(rowBase + rloc);
                orows[mi][half] = orow;
                float s = 0.f, sq = 0.f;
                #pragma unroll
                for (int ni = 0; ni < 4; ni++) {
                    int col = warpN * 32 + ni * 8 + 2 * tig;
                    const float2 r = *(const float2*)(resid + orow * CDIM + col);
                    float v0 = cc[mi][ni][half * 2 + 0] + bias[col]     + r.x;
                    float v1 = cc[mi][ni][half * 2 + 1] + bias[col + 1] + r.y;
                    cc[mi][ni][half * 2 + 0] = v0;
                    cc[mi][ni][half * 2 + 1] = v1;
                    *(float2*)(C + orow * CDIM + col) = make_float2(v0, v1);
                    s += v0 + v1; sq += v0 * v0 + v1 * v1;
                }
                s  += __shfl_xor_sync(0xffffffffu, s, 1);
                sq += __shfl_xor_sync(0xffffffffu, sq, 1);
                s  += __shfl_xor_sync(0xffffffffu, s, 2);
                sq += __shfl_xor_sync(0xffffffffu, sq, 2);
                if (tig == 0) {
                    atomicAdd(&red[2 * rloc],     s);
                    atomicAdd(&red[2 * rloc + 1], sq);
                }
            }
        }
        __syncthreads();
        #pragma unroll
        for (int mi = 0; mi < 2; mi++) {
            #pragma unroll
            for (int half = 0; half < 2; half++) {
                int rloc = warpM * 32 + mi * 16 + gid + half * 8;
                long orow = orows[mi][half];
                float mean = red[2 * rloc] * (1.0f / CDIM);
                float var  = red[2 * rloc + 1] * (1.0f / CDIM) - mean * mean;
                float rstd = rsqrtf(var + 1e-5f);
                #pragma unroll
                for (int ni = 0; ni < 4; ni++) {
                    int col = warpN * 32 + ni * 8 + 2 * tig;
                    float v0 = cc[mi][ni][half * 2 + 0];
                    float v1 = cc[mi][ni][half * 2 + 1];
                    float y0 = (v0 - mean) * rstd * gam[col]     + bet[col];
                    float y1 = (v1 - mean) * rstd * gam[col + 1] + bet[col + 1];
                    *(uint32_t*)(g_xw + orow * CDIM + col) = pack_bf2(y0, y1);
                }
            }
        }
        return;
    }

    // MODE 3: fc2 + residual -> fp32 out
    #pragma unroll
    for (int mi = 0; mi < 2; mi++) {
        #pragma unroll
        for (int half = 0; half < 2; half++) {
            long row = rowBase + warpM * 32 + mi * 16 + gid + half * 8;
            #pragma unroll
            for (int ni = 0; ni < 4; ni++) {
                int col = warpN * 32 + ni * 8 + 2 * tig;
                const float2 r = *(const float2*)(resid + row * CDIM + col);
                float v0 = cc[mi][ni][half * 2 + 0] + bias[col]     + r.x;
                float v1 = cc[mi][ni][half * 2 + 1] + bias[col + 1] + r.y;
                *(float2*)(C + row * CDIM + col) = make_float2(v0, v1);
            }
        }
    }
}

// ---------------------------------------------------------------------------
// BF16 tensor-core window attention (R9: aliased smem, 4 CTAs/SM)
// ---------------------------------------------------------------------------
#define AQS 40
#define PSS 120
#define NPAD 112
#define ATTN_ELEMS (128 * PSS + NPAD * AQS)   // 19840 bf16 = 39680 B
__global__ __launch_bounds__(128, 4)
void attn_kernel() {
    extern __shared__ bf16 asm_[];
    bf16* qs  = asm_;                          // [128][40]   (aliased by ps later)
    bf16* ks  = asm_ + 128 * AQS;              // [112][40]   (aliased by ps later)
    bf16* ps  = asm_;                          // [128][120]
    bf16* vsr = asm_ + 128 * PSS;              // [112][40]

    const int w = blockIdx.x;
    const int h = blockIdx.y;
    const int tid  = threadIdx.x;
    const int warp = tid >> 5;
    const int lane = tid & 31;
    const int gid = lane >> 2;
    const int tig = lane & 3;

    const bf16* base = g_qkv + (size_t)w * NTOK * QKVN + h * HD;

    for (int i = tid; i < NTOK * 4; i += 128) {
        int m = i >> 2, c = (i & 3) * 8;
        *(uint4*)&qs [m * AQS + c] = *(const uint4*)(base + m * QKVN + c);
        *(uint4*)&ks [m * AQS + c] = *(const uint4*)(base + m * QKVN + CDIM + c);
        *(uint4*)&vsr[m * AQS + c] = *(const uint4*)(base + m * QKVN + 2 * CDIM + c);
    }
    const uint4 z4 = make_uint4(0, 0, 0, 0);
    for (int i = tid; i < 30 * 4; i += 128) {
        int m = 98 + (i >> 2), c = (i & 3) * 8;
        *(uint4*)&qs[m * AQS + c] = z4;
        if (m < NPAD) {
            *(uint4*)&ks [m * AQS + c] = z4;
            *(uint4*)&vsr[m * AQS + c] = z4;
        }
    }
    __syncthreads();

    const int a_r = (lane & 7) + ((lane >> 3) & 1) * 8;
    const int a_k = (lane >> 4) * 8;
    const int b_n = (lane & 7) + (lane >> 4) * 8;
    const int b_k = ((lane >> 3) & 1) * 8;
    const int t_r = (lane & 7) + ((lane >> 3) & 1) * 8;
    const int t_c = (lane >> 4) * 8;

    float cc[2][14][4];
    #pragma unroll
    for (int mi = 0; mi < 2; mi++)
        #pragma unroll
        for (int ni = 0; ni < 14; ni++)
            #pragma unroll
            for (int e = 0; e < 4; e++) cc[mi][ni][e] = 0.f;

    #pragma unroll
    for (int ksx = 0; ksx < 2; ksx++) {
        const int kk = ksx * 16;
        uint32_t af[2][4];
        #pragma unroll
        for (int mi = 0; mi < 2; mi++)
            ldsm_x4(af[mi], qs + (warp * 32 + mi * 16 + a_r) * AQS + kk + a_k);
        #pragma unroll
        for (int np = 0; np < 7; np++) {
            uint32_t r4[4];
            ldsm_x4(r4, ks + (np * 16 + b_n) * AQS + kk + b_k);
            uint32_t b0[2] = { r4[0], r4[1] };
            uint32_t b1[2] = { r4[2], r4[3] };
            mma_bf16(cc[0][2 * np],     af[0], b0);
            mma_bf16(cc[1][2 * np],     af[1], b0);
            mma_bf16(cc[0][2 * np + 1], af[0], b1);
            mma_bf16(cc[1][2 * np + 1], af[1], b1);
        }
    }

    float rsum[2][2] = {{0.f, 0.f}, {0.f, 0.f}};
    const float* gb = g_bias + h * NTOK * NTOK;
    #pragma unroll
    for (int mi = 0; mi < 2; mi++) {
        int r0 = warp * 32 + mi * 16 + gid;
        int r1 = r0 + 8;
        const float* b0p = gb + (r0 < NTOK ? r0 : NTOK - 1) * NTOK;
        const float* b1p = gb + (r1 < NTOK ? r1 : NTOK - 1) * NTOK;
        #pragma unroll
        for (int ni = 0; ni < 14; ni++) {
            int c0 = ni * 8 + 2 * tig;
            int c1 = c0 + 1;
            int cc0 = c0 < NTOK ? c0 : NTOK - 1;
            int cc1 = c1 < NTOK ? c1 : NTOK - 1;
            float e;
            e = (c0 < NTOK) ? __expf(cc[mi][ni][0] + b0p[cc0]) : 0.f; cc[mi][ni][0] = e; rsum[mi][0] += e;
            e = (c1 < NTOK) ? __expf(cc[mi][ni][1] + b0p[cc1]) : 0.f; cc[mi][ni][1] = e; rsum[mi][0] += e;
            e = (c0 < NTOK) ? __expf(cc[mi][ni][2] + b1p[cc0]) : 0.f; cc[mi][ni][2] = e; rsum[mi][1] += e;
            e = (c1 < NTOK) ? __expf(cc[mi][ni][3] + b1p[cc1]) : 0.f; cc[mi][ni][3] = e; rsum[mi][1] += e;
        }
    }
    float inv[2][2];
    #pragma unroll
    for (int mi = 0; mi < 2; mi++)
        #pragma unroll
        for (int hf = 0; hf < 2; hf++) {
            float s = rsum[mi][hf];
            s += __shfl_xor_sync(0xffffffffu, s, 1);
            s += __shfl_xor_sync(0xffffffffu, s, 2);
            inv[mi][hf] = 1.0f / s;
        }

    __syncthreads();   // all warps done reading qs/ks before ps overwrites them

    #pragma unroll
    for (int mi = 0; mi < 2; mi++) {
        int r0 = warp * 32 + mi * 16 + gid;
        #pragma unroll
        for (int ni = 0; ni < 14; ni++) {
            int col = ni * 8 + 2 * tig;
            *(uint32_t*)&ps[r0 * PSS + col] =
                pack_bf2(cc[mi][ni][0] * inv[mi][0], cc[mi][ni][1] * inv[mi][0]);
            *(uint32_t*)&ps[(r0 + 8) * PSS + col] =
                pack_bf2(cc[mi][ni][2] * inv[mi][1], cc[mi][ni][3] * inv[mi][1]);
        }
    }
    __syncwarp();

    float oo[2][4][4];
    #pragma unroll
    for (int mi = 0; mi < 2; mi++)
        #pragma unroll
        for (int ni = 0; ni < 4; ni++)
            #pragma unroll
            for (int e = 0; e < 4; e++) oo[mi][ni][e] = 0.f;

    #pragma unroll
    for (int k2 = 0; k2 < 7; k2++) {
        const int kk = k2 * 16;
        uint32_t af[2][4];
        #pragma unroll
        for (int mi = 0; mi < 2; mi++)
            ldsm_x4(af[mi], ps + (warp * 32 + mi * 16 + a_r) * PSS + kk + a_k);
        #pragma unroll
        for (int np = 0; np < 2; np++) {
            int n0 = np * 16;
            uint32_t r4[4];
            ldsm_x4_t(r4, vsr + (kk + t_r) * AQS + n0 + t_c);
            uint32_t b0[2] = { r4[0], r4[1] };
            uint32_t b1[2] = { r4[2], r4[3] };
            mma_bf16(oo[0][2 * np],     af[0], b0);
            mma_bf16(oo[1][2 * np],     af[1], b0);
            mma_bf16(oo[0][2 * np + 1], af[0], b1);
            mma_bf16(oo[1][2 * np + 1], af[1], b1);
        }
    }

    #pragma unroll
    for (int mi = 0; mi < 2; mi++) {
        #pragma unroll
        for (int hf = 0; hf < 2; hf++) {
            int row = warp * 32 + mi * 16 + gid + hf * 8;
            if (row < NTOK) {
                bf16* op = g_attn + ((size_t)w * NTOK + row) * CDIM + h * HD;
                #pragma unroll
                for (int ni = 0; ni < 4; ni++) {
                    int col = ni * 8 + 2 * tig;
                    *(uint32_t*)(op + col) =
                        pack_bf2(oo[mi][ni][hf * 2], oo[mi][ni][hf * 2 + 1]);
                }
            }
        }
    }
}

// ---------------------------------------------------------------------------
// launcher
// ---------------------------------------------------------------------------
extern "C" void kernel_launch(void* const* d_in, const int* in_sizes, int n_in,
                              void* d_out, int out_size) {
    const float* x          = (const float*)d_in[0];
    const float* norm1_w    = (const float*)d_in[1];
    const float* norm1_b    = (const float*)d_in[2];
    const float* qkv_w      = (const float*)d_in[3];
    const float* qkv_b      = (const float*)d_in[4];
    const float* bias_table = (const float*)d_in[5];
    const float* proj_w     = (const float*)d_in[6];
    const float* proj_b     = (const float*)d_in[7];
    const float* norm2_w    = (const float*)d_in[8];
    const float* norm2_b    = (const float*)d_in[9];
    const float* fc1_w      = (const float*)d_in[10];
    const float* fc1_b      = (const float*)d_in[11];
    const float* fc2_w      = (const float*)d_in[12];
    const float* fc2_b      = (const float*)d_in[13];
    const int*   rel_index  = (const int*)d_in[14];
    float* out = (float*)d_out;

    bf16 *p_xw, *p_qkv, *p_attn, *p_h;
    bf16 *p_wq, *p_wp, *p_w1, *p_w2;
    float *p_x2;
    cudaGetSymbolAddress((void**)&p_xw,   g_xw);
    cudaGetSymbolAddress((void**)&p_qkv,  g_qkv);
    cudaGetSymbolAddress((void**)&p_attn, g_attn);
    cudaGetSymbolAddress((void**)&p_x2,   g_x2);
    cudaGetSymbolAddress((void**)&p_h,    g_h);
    cudaGetSymbolAddress((void**)&p_wq,   g_wq);
    cudaGetSymbolAddress((void**)&p_wp,   g_wp);
    cudaGetSymbolAddress((void**)&p_w1,   g_w1);
    cudaGetSymbolAddress((void**)&p_w2,   g_w2);

    const int GEMM_SMEM  = 3 * G_STAGE   * (int)sizeof(bf16);  // 61440
    const int G64_SMEM   = 3 * G64_STAGE * (int)sizeof(bf16);  // 46080
    const int ATTN_SMEM  = ATTN_ELEMS * (int)sizeof(bf16);     // 39680
    cudaFuncSetAttribute((const void*)gemm_kernel<0,128>,   cudaFuncAttributeMaxDynamicSharedMemorySize, GEMM_SMEM);
    cudaFuncSetAttribute((const void*)gemm_kernel<2,128>,   cudaFuncAttributeMaxDynamicSharedMemorySize, GEMM_SMEM);
    cudaFuncSetAttribute((const void*)gemm64_kernel<1,128>, cudaFuncAttributeMaxDynamicSharedMemorySize, G64_SMEM);
    cudaFuncSetAttribute((const void*)gemm64_kernel<3,512>, cudaFuncAttributeMaxDynamicSharedMemorySize, G64_SMEM);
    cudaFuncSetAttribute((const void*)attn_kernel,          cudaFuncAttributeMaxDynamicSharedMemorySize, ATTN_SMEM);

    // 0) weight conversion + bias gather
    cvt_weights_kernel<<<49152 / 256, 256>>>(qkv_w, proj_w, fc1_w, fc2_w);
    bias_gather_kernel<<<dim3(NTOK, NH), NTOK>>>(bias_table, rel_index);

    // 1) LN1 + window partition (fp32 -> bf16)
    ln_kernel<true><<<TOK / 8, 256>>>(x, norm1_w, norm1_b, p_xw);

    // 2) QKV gemm (+ q scale), bf16 out
    gemm_kernel<0,128><<<dim3(QKVN / 128, TOK / 128), 256, GEMM_SMEM>>>(
        p_xw, p_wq, qkv_b, p_qkv, QKVN);

    // 3) window attention (bf16 tensor cores)
    attn_kernel<<<dim3(NWIN, NH), 128, ATTN_SMEM>>>();

    // 4) proj gemm + window reverse + residual(x) -> g_x2 (fp32) + fused LN2 -> g_xw (bf16)
    gemm64_kernel<1,128><<<TOK / 64, 256, G64_SMEM>>>(
        p_attn, p_wp, proj_b, x, norm2_w, norm2_b, p_x2);

    // 5) fc1 + exact GELU, bf16 out
    gemm_kernel<2,128><<<dim3(CH / 128, TOK / 128), 256, GEMM_SMEM>>>(
        p_xw, p_w1, fc1_b, p_h, CH);

    // 6) fc2 + residual(g_x2) -> d_out (fp32)
    gemm64_kernel<3,512><<<TOK / 64, 256, G64_SMEM>>>(
        p_h, p_w2, fc2_b, p_x2, nullptr, nullptr, out);

    (void)in_sizes; (void)n_in; (void)out_size;
}